// round 3
// baseline (speedup 1.0000x reference)
#include <cuda_runtime.h>
#include <math.h>

// ---------------- problem constants ----------------
#define BATCH 4
#define CC    512
#define HH    64
#define WW    64
#define PP    (HH*WW)          // 4096 pixels per image
#define NP    (BATCH*PP)       // 16384 total pixels
#define NHEAD 16
#define HD    32               // head dim
#define BS    8
#define HALO  3
#define WIN   14
#define NWIN  (WIN*WIN)        // 196
#define NBW   (WW/BS)          // 8
#define NB    ((HH/BS)*(WW/BS))// 64 blocks per image
#define MLPH  2048
#define EPSLN 1e-5f

// ---------------- scratch (device globals; no allocs allowed) ----------------
// Overlap plan (element offsets into g_big, NP*CC = 8388608 floats):
//   xT : [0,        8388608)   live: step1 .. step5
//   q  : [8388608, 16777216)   live: step3 .. step5
//   kv : [16777216, 33554432)  live: step4 .. step5
//   h1 : [0,       33554432)   live: step7 .. step8   (aliases xT|q|kv - disjoint lifetime)
#define ELEM_XC (NP*CC)
__device__ float g_big [(size_t)NP*MLPH];   // 128 MB
__device__ float g_ln  [ELEM_XC];           // LN output (ln1 then ln2)
__device__ float g_xres[ELEM_XC];           // x + gamma1*a (NHWC)
__device__ float g_y   [ELEM_XC];           // fc2 output NHWC

// ---------------- NCHW -> NHWC transpose ----------------
__global__ void k_transpose_in(const float* __restrict__ x, float* __restrict__ xT) {
    __shared__ float t[32][33];
    int b  = blockIdx.z;
    int p0 = blockIdx.x * 32;   // pixel
    int c0 = blockIdx.y * 32;   // channel
    int tx = threadIdx.x, ty = threadIdx.y;      // 32 x 8
    const float* src = x + (size_t)b * CC * PP;
    #pragma unroll
    for (int i = 0; i < 32; i += 8)
        t[ty + i][tx] = src[(size_t)(c0 + ty + i) * PP + p0 + tx];
    __syncthreads();
    float* dst = xT + (size_t)b * PP * CC;
    #pragma unroll
    for (int i = 0; i < 32; i += 8)
        dst[(size_t)(p0 + ty + i) * CC + c0 + tx] = t[tx][ty + i];
}

// ---------------- LayerNorm over channel (contiguous in NHWC) ----------------
__global__ void k_ln(const float* __restrict__ in, const float* __restrict__ g,
                     const float* __restrict__ bta, float* __restrict__ out) {
    int pix = blockIdx.x;
    int t   = threadIdx.x;     // 128 threads, 4 channels each
    const float4* row = (const float4*)(in + (size_t)pix * CC);
    float4 v = row[t];
    float s  = v.x + v.y + v.z + v.w;
    float s2 = v.x*v.x + v.y*v.y + v.z*v.z + v.w*v.w;
    #pragma unroll
    for (int o = 16; o; o >>= 1) {
        s  += __shfl_xor_sync(0xffffffffu, s,  o);
        s2 += __shfl_xor_sync(0xffffffffu, s2, o);
    }
    __shared__ float sh[4][2];
    int warp = t >> 5, lane = t & 31;
    if (lane == 0) { sh[warp][0] = s; sh[warp][1] = s2; }
    __syncthreads();
    s  = sh[0][0] + sh[1][0] + sh[2][0] + sh[3][0];
    s2 = sh[0][1] + sh[1][1] + sh[2][1] + sh[3][1];
    float mu = s * (1.0f / CC);
    float var = s2 * (1.0f / CC) - mu * mu;
    float rs = rsqrtf(var + EPSLN);
    float4 gv = ((const float4*)g)[t];
    float4 bv = ((const float4*)bta)[t];
    float4 o4;
    o4.x = (v.x - mu) * rs * gv.x + bv.x;
    o4.y = (v.y - mu) * rs * gv.y + bv.y;
    o4.z = (v.z - mu) * rs * gv.z + bv.z;
    o4.w = (v.w - mu) * rs * gv.w + bv.w;
    ((float4*)(out + (size_t)pix * CC))[t] = o4;
}

// ---------------- SGEMM 128x128x8, 8x8 register tile, double buffered --------
// epi: 0 = none, 1 = +bias, 2 = +bias then exact GELU
__global__ void __launch_bounds__(256)
k_sgemm(const float* __restrict__ A, const float* __restrict__ B,
        const float* __restrict__ bias, float* __restrict__ C,
        int M, int N, int K, int epi) {
    __shared__ float As[2][8][128];
    __shared__ float Bs[2][8][128];
    int tid = threadIdx.x;
    int bm = blockIdx.y << 7, bn = blockIdx.x << 7;

    int arow = tid >> 1, acol = (tid & 1) << 2;   // A tile 128x8
    int brow = tid >> 5, bcol = (tid & 31) << 2;  // B tile 8x128
    const float* Ap = A + (size_t)(bm + arow) * K + acol;
    const float* Bp = B + (size_t)brow * N + bn + bcol;

    float4 a4 = *(const float4*)Ap;
    float4 b4 = *(const float4*)Bp;
    As[0][acol + 0][arow] = a4.x; As[0][acol + 1][arow] = a4.y;
    As[0][acol + 2][arow] = a4.z; As[0][acol + 3][arow] = a4.w;
    *(float4*)&Bs[0][brow][bcol] = b4;
    __syncthreads();

    float acc[8][8];
    #pragma unroll
    for (int i = 0; i < 8; ++i)
        #pragma unroll
        for (int j = 0; j < 8; ++j) acc[i][j] = 0.f;

    int tx = (tid & 15) << 3;   // 0..120 (multiple of 8 -> float4 aligned)
    int ty = (tid >> 4) << 3;   // 0..120
    int nT = K >> 3;

    for (int t = 0; t < nT; ++t) {
        int cur = t & 1;
        if (t + 1 < nT) {
            a4 = *(const float4*)(Ap + (size_t)(t + 1) * 8);
            b4 = *(const float4*)(Bp + (size_t)(t + 1) * 8 * N);
        }
        #pragma unroll
        for (int k = 0; k < 8; ++k) {
            float4 av0 = *(const float4*)&As[cur][k][ty];
            float4 av1 = *(const float4*)&As[cur][k][ty + 4];
            float4 bv0 = *(const float4*)&Bs[cur][k][tx];
            float4 bv1 = *(const float4*)&Bs[cur][k][tx + 4];
            float ar[8] = {av0.x, av0.y, av0.z, av0.w, av1.x, av1.y, av1.z, av1.w};
            float br[8] = {bv0.x, bv0.y, bv0.z, bv0.w, bv1.x, bv1.y, bv1.z, bv1.w};
            #pragma unroll
            for (int i = 0; i < 8; ++i)
                #pragma unroll
                for (int j = 0; j < 8; ++j) acc[i][j] = fmaf(ar[i], br[j], acc[i][j]);
        }
        if (t + 1 < nT) {
            int nxt = cur ^ 1;
            As[nxt][acol + 0][arow] = a4.x; As[nxt][acol + 1][arow] = a4.y;
            As[nxt][acol + 2][arow] = a4.z; As[nxt][acol + 3][arow] = a4.w;
            *(float4*)&Bs[nxt][brow][bcol] = b4;
            __syncthreads();
        }
    }

    // epilogue
    #pragma unroll
    for (int i = 0; i < 8; ++i) {
        float* crow = C + (size_t)(bm + ty + i) * N + bn + tx;
        #pragma unroll
        for (int j4 = 0; j4 < 2; ++j4) {
            float4 o;
            float v0 = acc[i][j4 * 4 + 0], v1 = acc[i][j4 * 4 + 1];
            float v2 = acc[i][j4 * 4 + 2], v3 = acc[i][j4 * 4 + 3];
            if (epi >= 1) {
                const float* bp = bias + bn + tx + j4 * 4;
                v0 += bp[0]; v1 += bp[1]; v2 += bp[2]; v3 += bp[3];
            }
            if (epi == 2) {
                v0 = 0.5f * v0 * (1.f + erff(v0 * 0.70710678118654752f));
                v1 = 0.5f * v1 * (1.f + erff(v1 * 0.70710678118654752f));
                v2 = 0.5f * v2 * (1.f + erff(v2 * 0.70710678118654752f));
                v3 = 0.5f * v3 * (1.f + erff(v3 * 0.70710678118654752f));
            }
            o.x = v0; o.y = v1; o.z = v2; o.w = v3;
            *(float4*)(crow + j4 * 4) = o;
        }
    }
}

// ---------------- halo attention: one CTA per (b, head, block) ----------------
// Fused epilogue: writes xres = xT + gamma1[c] * attn_out directly.
// dyn smem layout (floats): sq[64][33] | sk[196][32] | sv[196][32] | sc[64][197]
#define SQ_OFF 0
#define SK_OFF (64*33)
#define SV_OFF (SK_OFF + NWIN*HD)
#define SC_OFF (SV_OFF + NWIN*HD)
#define ATT_SMEM_FLOATS (SC_OFF + 64*197)

__global__ void __launch_bounds__(256)
k_attn(const float* __restrict__ q, const float* __restrict__ kv,
       const float* __restrict__ xT, const float* __restrict__ gamma1,
       float* __restrict__ xres) {
    extern __shared__ float sm[];
    float* sq = sm + SQ_OFF;
    float* sk = sm + SK_OFF;
    float* sv = sm + SV_OFF;
    float* sc = sm + SC_OFF;

    int blk  = blockIdx.x;          // 0..63
    int head = blockIdx.y;
    int b    = blockIdx.z;
    int by0 = (blk / NBW) * BS;
    int bx0 = (blk % NBW) * BS;
    int tid = threadIdx.x;

    // load q tile 64x32
    for (int idx = tid; idx < 64 * HD; idx += 256) {
        int r = idx >> 5, d = idx & 31;
        int y = by0 + (r >> 3), x = bx0 + (r & 7);
        sq[r * 33 + d] = q[((size_t)b * PP + (size_t)y * WW + x) * CC + head * HD + d];
    }
    // load k/v window 196x32 (OOB -> 0, matching zero padding incl. softmax)
    for (int idx = tid; idx < NWIN * HD; idx += 256) {
        int r = idx >> 5, d = idx & 31;
        int y = by0 - HALO + r / WIN;
        int x = bx0 - HALO + r % WIN;
        float kk = 0.f, vv = 0.f;
        if (y >= 0 && y < HH && x >= 0 && x < WW) {
            size_t base = ((size_t)b * PP + (size_t)y * WW + x) * (2 * CC) + head * HD + d;
            kk = kv[base];
            vv = kv[base + CC];
        }
        sk[r * HD + d] = kk;
        sv[r * HD + d] = vv;
    }
    __syncthreads();

    // scores: thread (qi, kgroup)
    int qi = tid & 63;
    int kg = tid >> 6;      // 0..3
    float qreg[HD];
    #pragma unroll
    for (int d = 0; d < HD; ++d) qreg[d] = sq[qi * 33 + d];
    const float scale = 0.1767766952966369f;  // 1/sqrt(32)
    for (int kj = kg; kj < NWIN; kj += 4) {
        float acc = 0.f;
        #pragma unroll
        for (int d = 0; d < HD; ++d) acc = fmaf(qreg[d], sk[kj * HD + d], acc);
        sc[qi * 197 + kj] = acc * scale;
    }
    __syncthreads();

    // softmax: warp per row
    int warp = tid >> 5, lane = tid & 31;
    for (int r = warp; r < 64; r += 8) {
        float m = -1e30f;
        for (int j = lane; j < NWIN; j += 32) m = fmaxf(m, sc[r * 197 + j]);
        #pragma unroll
        for (int o = 16; o; o >>= 1) m = fmaxf(m, __shfl_xor_sync(0xffffffffu, m, o));
        float sum = 0.f;
        for (int j = lane; j < NWIN; j += 32) {
            float e = __expf(sc[r * 197 + j] - m);
            sc[r * 197 + j] = e;
            sum += e;
        }
        #pragma unroll
        for (int o = 16; o; o >>= 1) sum += __shfl_xor_sync(0xffffffffu, sum, o);
        float inv = 1.f / sum;
        for (int j = lane; j < NWIN; j += 32) sc[r * 197 + j] *= inv;
    }
    __syncthreads();

    // out = attn @ V : thread (qi, dgroup of 8); fused residual epilogue
    float acc[8];
    #pragma unroll
    for (int i = 0; i < 8; ++i) acc[i] = 0.f;
    int d0 = kg * 8;
    for (int kj = 0; kj < NWIN; ++kj) {
        float s = sc[qi * 197 + kj];
        #pragma unroll
        for (int i = 0; i < 8; ++i) acc[i] = fmaf(s, sv[kj * HD + d0 + i], acc[i]);
    }
    int y = by0 + (qi >> 3), x = bx0 + (qi & 7);
    size_t off = ((size_t)b * PP + (size_t)y * WW + x) * CC + head * HD + d0;
    float4 xv0 = *(const float4*)(xT + off);
    float4 xv1 = *(const float4*)(xT + off + 4);
    float4 gv0 = *(const float4*)(gamma1 + head * HD + d0);
    float4 gv1 = *(const float4*)(gamma1 + head * HD + d0 + 4);
    float4 o0, o1;
    o0.x = xv0.x + gv0.x * acc[0];
    o0.y = xv0.y + gv0.y * acc[1];
    o0.z = xv0.z + gv0.z * acc[2];
    o0.w = xv0.w + gv0.w * acc[3];
    o1.x = xv1.x + gv1.x * acc[4];
    o1.y = xv1.y + gv1.y * acc[5];
    o1.z = xv1.z + gv1.z * acc[6];
    o1.w = xv1.w + gv1.w * acc[7];
    *(float4*)(xres + off)     = o0;
    *(float4*)(xres + off + 4) = o1;
}

// ---------- final: out(NCHW) = xres + gamma2[c]*y, with NHWC->NCHW transpose ----------
__global__ void k_final(const float* __restrict__ xres, const float* __restrict__ y,
                        const float* __restrict__ gamma2, float* __restrict__ out) {
    __shared__ float t[32][33];
    int b  = blockIdx.z;
    int p0 = blockIdx.x * 32;
    int c0 = blockIdx.y * 32;
    int tx = threadIdx.x, ty = threadIdx.y;     // 32 x 8
    const float* xb = xres + (size_t)b * PP * CC;
    const float* yb = y    + (size_t)b * PP * CC;
    #pragma unroll
    for (int i = 0; i < 32; i += 8) {
        int p = p0 + ty + i, c = c0 + tx;
        size_t off = (size_t)p * CC + c;
        t[ty + i][tx] = xb[off] + gamma2[c] * yb[off];
    }
    __syncthreads();
    float* ob = out + (size_t)b * CC * PP;
    #pragma unroll
    for (int i = 0; i < 32; i += 8)
        ob[(size_t)(c0 + ty + i) * PP + p0 + tx] = t[tx][ty + i];
}

// ---------------- launcher ----------------
extern "C" void kernel_launch(void* const* d_in, const int* in_sizes, int n_in,
                              void* d_out, int out_size) {
    const float* x      = (const float*)d_in[0];
    const float* g1     = (const float*)d_in[1];
    const float* b1     = (const float*)d_in[2];
    const float* w_q    = (const float*)d_in[3];
    const float* w_kv   = (const float*)d_in[4];
    const float* gamma1 = (const float*)d_in[5];
    const float* g2     = (const float*)d_in[6];
    const float* b2     = (const float*)d_in[7];
    const float* w_fc1  = (const float*)d_in[8];
    const float* b_fc1  = (const float*)d_in[9];
    const float* w_fc2  = (const float*)d_in[10];
    const float* b_fc2  = (const float*)d_in[11];
    const float* gamma2 = (const float*)d_in[12];
    float* out = (float*)d_out;

    float *big, *ln, *xres, *yb;
    cudaGetSymbolAddress((void**)&big,  g_big);
    cudaGetSymbolAddress((void**)&ln,   g_ln);
    cudaGetSymbolAddress((void**)&xres, g_xres);
    cudaGetSymbolAddress((void**)&yb,   g_y);
    float* xT = big;                     // [0, 8M)
    float* q  = big + (size_t)ELEM_XC;   // [8M, 16M)
    float* kv = big + (size_t)2*ELEM_XC; // [16M, 32M)
    float* h1 = big;                     // aliases xT|q|kv (disjoint lifetime)

    const int attnSmem = ATT_SMEM_FLOATS * (int)sizeof(float);   // ~109 KB
    cudaFuncSetAttribute(k_attn, cudaFuncAttributeMaxDynamicSharedMemorySize, attnSmem);

    dim3 tb32(32, 8);
    dim3 gT(PP / 32, CC / 32, BATCH);

    // 1) NCHW -> NHWC
    k_transpose_in<<<gT, tb32>>>(x, xT);
    // 2) ln1
    k_ln<<<NP, 128>>>(xT, g1, b1, ln);
    // 3) q = ln1 @ w_q
    k_sgemm<<<dim3(CC / 128, NP / 128), 256>>>(ln, w_q, nullptr, q, NP, CC, CC, 0);
    // 4) kv = ln1 @ w_kv
    k_sgemm<<<dim3(2 * CC / 128, NP / 128), 256>>>(ln, w_kv, nullptr, kv, NP, 2 * CC, CC, 0);
    // 5) halo attention + fused residual-1 (writes xres)
    k_attn<<<dim3(NB, NHEAD, BATCH), 256, attnSmem>>>(q, kv, xT, gamma1, xres);
    // 6) ln2
    k_ln<<<NP, 128>>>(xres, g2, b2, ln);
    // 7) fc1 + bias + gelu
    k_sgemm<<<dim3(MLPH / 128, NP / 128), 256>>>(ln, w_fc1, b_fc1, h1, NP, MLPH, CC, 2);
    // 8) fc2 + bias
    k_sgemm<<<dim3(CC / 128, NP / 128), 256>>>(h1, w_fc2, b_fc2, yb, NP, CC, MLPH, 1);
    // 9) final residual + NHWC -> NCHW
    k_final<<<gT, tb32>>>(xres, yb, gamma2, out);
}

// round 6
// speedup vs baseline: 2.0332x; 2.0332x over previous
#include <cuda_runtime.h>
#include <cuda_bf16.h>
#include <math.h>
#include <stdint.h>

// ---------------- problem constants ----------------
#define BATCH 4
#define CC    512
#define HH    64
#define WW    64
#define PP    (HH*WW)          // 4096 pixels per image
#define NP    (BATCH*PP)       // 16384 total pixels
#define NHEAD 16
#define HD    32               // head dim
#define BS    8
#define HALO  3
#define WIN   14
#define NWIN  (WIN*WIN)        // 196
#define NBW   (WW/BS)          // 8
#define NB    ((HH/BS)*(WW/BS))// 64 blocks per image
#define MLPH  2048
#define EPSLN 1e-5f

// ---------------- scratch (device globals; no allocs allowed) ----------------
#define ELEM_XC (NP*CC)
__device__ float g_big [(size_t)NP*MLPH];   // 128 MB; xT|q|kv overlay, then h1
__device__ float g_ln  [ELEM_XC];           // LN output (ln1 then ln2)
__device__ float g_xres[ELEM_XC];           // x + gamma1*a (NHWC)
__device__ float g_y   [ELEM_XC];           // fc2 output NHWC

// ---------------- NCHW -> NHWC transpose ----------------
__global__ void k_transpose_in(const float* __restrict__ x, float* __restrict__ xT) {
    __shared__ float t[32][33];
    int b  = blockIdx.z;
    int p0 = blockIdx.x * 32;
    int c0 = blockIdx.y * 32;
    int tx = threadIdx.x, ty = threadIdx.y;      // 32 x 8
    const float* src = x + (size_t)b * CC * PP;
    #pragma unroll
    for (int i = 0; i < 32; i += 8)
        t[ty + i][tx] = src[(size_t)(c0 + ty + i) * PP + p0 + tx];
    __syncthreads();
    float* dst = xT + (size_t)b * PP * CC;
    #pragma unroll
    for (int i = 0; i < 32; i += 8)
        dst[(size_t)(p0 + ty + i) * CC + c0 + tx] = t[tx][ty + i];
}

// ---------------- LayerNorm over channel (contiguous in NHWC) ----------------
__global__ void k_ln(const float* __restrict__ in, const float* __restrict__ g,
                     const float* __restrict__ bta, float* __restrict__ out) {
    int pix = blockIdx.x;
    int t   = threadIdx.x;     // 128 threads, 4 channels each
    const float4* row = (const float4*)(in + (size_t)pix * CC);
    float4 v = row[t];
    float s  = v.x + v.y + v.z + v.w;
    float s2 = v.x*v.x + v.y*v.y + v.z*v.z + v.w*v.w;
    #pragma unroll
    for (int o = 16; o; o >>= 1) {
        s  += __shfl_xor_sync(0xffffffffu, s,  o);
        s2 += __shfl_xor_sync(0xffffffffu, s2, o);
    }
    __shared__ float sh[4][2];
    int warp = t >> 5, lane = t & 31;
    if (lane == 0) { sh[warp][0] = s; sh[warp][1] = s2; }
    __syncthreads();
    s  = sh[0][0] + sh[1][0] + sh[2][0] + sh[3][0];
    s2 = sh[0][1] + sh[1][1] + sh[2][1] + sh[3][1];
    float mu = s * (1.0f / CC);
    float var = s2 * (1.0f / CC) - mu * mu;
    float rs = rsqrtf(var + EPSLN);
    float4 gv = ((const float4*)g)[t];
    float4 bv = ((const float4*)bta)[t];
    float4 o4;
    o4.x = (v.x - mu) * rs * gv.x + bv.x;
    o4.y = (v.y - mu) * rs * gv.y + bv.y;
    o4.z = (v.z - mu) * rs * gv.z + bv.z;
    o4.w = (v.w - mu) * rs * gv.w + bv.w;
    ((float4*)(out + (size_t)pix * CC))[t] = o4;
}

// ---------------- bf16 tensor-core GEMM 128x128x32 ----------------
// C[M,N] = A[M,K] @ B[K,N] (fp32 in, bf16 mma, fp32 accum/out)
// 256 threads = 8 warps (2 x 4), warp tile 64x32, mma.m16n8k16.
// epi: 0 = none, 1 = +bias, 2 = +bias then exact GELU
#define SPAD 40   // bf16 row stride for both A(row-major) and B(n-major) tiles

__device__ __forceinline__ void mma_bf16(float* c, uint32_t a0, uint32_t a1,
                                         uint32_t a2, uint32_t a3,
                                         uint32_t b0, uint32_t b1) {
    asm volatile(
        "mma.sync.aligned.m16n8k16.row.col.f32.bf16.bf16.f32 "
        "{%0,%1,%2,%3}, {%4,%5,%6,%7}, {%8,%9}, {%0,%1,%2,%3};\n"
        : "+f"(c[0]), "+f"(c[1]), "+f"(c[2]), "+f"(c[3])
        : "r"(a0), "r"(a1), "r"(a2), "r"(a3), "r"(b0), "r"(b1));
}

__global__ void __launch_bounds__(256)
k_gemm_bf16(const float* __restrict__ A, const float* __restrict__ B,
            const float* __restrict__ bias, float* __restrict__ C,
            int M, int N, int K, int epi) {
    __shared__ __align__(16) __nv_bfloat16 As[2][128 * SPAD];
    __shared__ __align__(16) __nv_bfloat16 Bsm[2][128 * SPAD];

    int tid = threadIdx.x;
    int bm = blockIdx.y << 7, bn = blockIdx.x << 7;

    // ---- staging maps ----
    int arow = tid >> 1;               // 0..127
    int ac16 = (tid & 1) * 16;         // col half
    const float* Ap = A + (size_t)(bm + arow) * K + ac16;
    int bk  = tid >> 3;                // 0..31 (k row)
    int bq  = (tid & 7) * 4;           // n start (stride-32 across i)
    const float* Bp = B + (size_t)bk * N + bn + bq;

    float4 a4[4], b4[4];

    auto loadg = [&](int k0) {
        #pragma unroll
        for (int i = 0; i < 4; ++i)
            a4[i] = *(const float4*)(Ap + k0 + 4 * i);
        #pragma unroll
        for (int i = 0; i < 4; ++i)
            b4[i] = *(const float4*)(Bp + (size_t)k0 * N + 32 * i);
    };
    auto store_s = [&](int buf) {
        #pragma unroll
        for (int i = 0; i < 4; ++i) {
            int c = ac16 + 4 * i;
            __nv_bfloat162 p0 = __floats2bfloat162_rn(a4[i].x, a4[i].y);
            __nv_bfloat162 p1 = __floats2bfloat162_rn(a4[i].z, a4[i].w);
            *(uint32_t*)&As[buf][arow * SPAD + c]     = *(uint32_t*)&p0;
            *(uint32_t*)&As[buf][arow * SPAD + c + 2] = *(uint32_t*)&p1;
        }
        #pragma unroll
        for (int i = 0; i < 4; ++i) {
            int n = bq + 32 * i;
            Bsm[buf][(n + 0) * SPAD + bk] = __float2bfloat16(b4[i].x);
            Bsm[buf][(n + 1) * SPAD + bk] = __float2bfloat16(b4[i].y);
            Bsm[buf][(n + 2) * SPAD + bk] = __float2bfloat16(b4[i].z);
            Bsm[buf][(n + 3) * SPAD + bk] = __float2bfloat16(b4[i].w);
        }
    };

    loadg(0);
    store_s(0);
    __syncthreads();

    float acc[4][4][4];
    #pragma unroll
    for (int a = 0; a < 4; ++a)
        #pragma unroll
        for (int b = 0; b < 4; ++b)
            #pragma unroll
            for (int cI = 0; cI < 4; ++cI) acc[a][b][cI] = 0.f;

    int lane = tid & 31, warp = tid >> 5;
    int wm = (warp & 1) * 64;        // m offset of warp tile
    int wn = (warp >> 1) * 32;       // n offset of warp tile
    int gid = lane >> 2, tig = lane & 3;

    int nT = K >> 5;
    for (int t = 0; t < nT; ++t) {
        int cur = t & 1;
        if (t + 1 < nT) loadg((t + 1) * 32);

        const uint32_t* As32 = (const uint32_t*)As[cur];
        const uint32_t* Bs32 = (const uint32_t*)Bsm[cur];

        #pragma unroll
        for (int ks = 0; ks < 2; ++ks) {
            int kb = ks * 16;
            uint32_t bfr[4][2];
            #pragma unroll
            for (int nf = 0; nf < 4; ++nf) {
                int n = wn + nf * 8 + gid;
                int base = n * 20 + (kb >> 1) + tig;   // uint32 index
                bfr[nf][0] = Bs32[base];
                bfr[nf][1] = Bs32[base + 4];
            }
            #pragma unroll
            for (int mf = 0; mf < 4; ++mf) {
                int r = wm + mf * 16 + gid;
                int base = r * 20 + (kb >> 1) + tig;
                uint32_t a0 = As32[base];
                uint32_t a1 = As32[base + 8 * 20];
                uint32_t a2 = As32[base + 4];
                uint32_t a3 = As32[base + 8 * 20 + 4];
                #pragma unroll
                for (int nf = 0; nf < 4; ++nf)
                    mma_bf16(acc[mf][nf], a0, a1, a2, a3, bfr[nf][0], bfr[nf][1]);
            }
        }

        if (t + 1 < nT) store_s(cur ^ 1);
        __syncthreads();
    }

    // ---- epilogue ----
    #pragma unroll
    for (int mf = 0; mf < 4; ++mf) {
        #pragma unroll
        for (int nf = 0; nf < 4; ++nf) {
            int row0 = bm + wm + mf * 16 + gid;
            int col  = bn + wn + nf * 8 + 2 * tig;
            float v[4] = {acc[mf][nf][0], acc[mf][nf][1],
                          acc[mf][nf][2], acc[mf][nf][3]};
            if (epi >= 1) {
                float bb0 = bias[col], bb1 = bias[col + 1];
                v[0] += bb0; v[1] += bb1; v[2] += bb0; v[3] += bb1;
            }
            if (epi == 2) {
                #pragma unroll
                for (int i = 0; i < 4; ++i)
                    v[i] = 0.5f * v[i] * (1.f + erff(v[i] * 0.70710678118654752f));
            }
            float2 lo = {v[0], v[1]}, hi = {v[2], v[3]};
            *(float2*)(C + (size_t)row0 * N + col)       = lo;
            *(float2*)(C + (size_t)(row0 + 8) * N + col) = hi;
        }
    }
}

// ---------------- halo attention: one CTA per (b, head, block) ----------------
// Fused epilogue: writes xres = xT + gamma1[c] * attn_out directly.
#define SQ_OFF 0
#define SK_OFF (64*33)
#define SV_OFF (SK_OFF + NWIN*HD)
#define SC_OFF (SV_OFF + NWIN*HD)
#define ATT_SMEM_FLOATS (SC_OFF + 64*197)

__global__ void __launch_bounds__(256)
k_attn(const float* __restrict__ q, const float* __restrict__ kv,
       const float* __restrict__ xT, const float* __restrict__ gamma1,
       float* __restrict__ xres) {
    extern __shared__ float sm[];
    float* sq = sm + SQ_OFF;
    float* sk = sm + SK_OFF;
    float* sv = sm + SV_OFF;
    float* sc = sm + SC_OFF;

    int blk  = blockIdx.x;
    int head = blockIdx.y;
    int b    = blockIdx.z;
    int by0 = (blk / NBW) * BS;
    int bx0 = (blk % NBW) * BS;
    int tid = threadIdx.x;

    for (int idx = tid; idx < 64 * HD; idx += 256) {
        int r = idx >> 5, d = idx & 31;
        int y = by0 + (r >> 3), x = bx0 + (r & 7);
        sq[r * 33 + d] = q[((size_t)b * PP + (size_t)y * WW + x) * CC + head * HD + d];
    }
    for (int idx = tid; idx < NWIN * HD; idx += 256) {
        int r = idx >> 5, d = idx & 31;
        int y = by0 - HALO + r / WIN;
        int x = bx0 - HALO + r % WIN;
        float kk = 0.f, vv = 0.f;
        if (y >= 0 && y < HH && x >= 0 && x < WW) {
            size_t base = ((size_t)b * PP + (size_t)y * WW + x) * (2 * CC) + head * HD + d;
            kk = kv[base];
            vv = kv[base + CC];
        }
        sk[r * HD + d] = kk;
        sv[r * HD + d] = vv;
    }
    __syncthreads();

    int qi = tid & 63;
    int kg = tid >> 6;
    float qreg[HD];
    #pragma unroll
    for (int d = 0; d < HD; ++d) qreg[d] = sq[qi * 33 + d];
    const float scale = 0.1767766952966369f;
    for (int kj = kg; kj < NWIN; kj += 4) {
        float a = 0.f;
        #pragma unroll
        for (int d = 0; d < HD; ++d) a = fmaf(qreg[d], sk[kj * HD + d], a);
        sc[qi * 197 + kj] = a * scale;
    }
    __syncthreads();

    int warp = tid >> 5, lane = tid & 31;
    for (int r = warp; r < 64; r += 8) {
        float m = -1e30f;
        for (int j = lane; j < NWIN; j += 32) m = fmaxf(m, sc[r * 197 + j]);
        #pragma unroll
        for (int o = 16; o; o >>= 1) m = fmaxf(m, __shfl_xor_sync(0xffffffffu, m, o));
        float sum = 0.f;
        for (int j = lane; j < NWIN; j += 32) {
            float e = __expf(sc[r * 197 + j] - m);
            sc[r * 197 + j] = e;
            sum += e;
        }
        #pragma unroll
        for (int o = 16; o; o >>= 1) sum += __shfl_xor_sync(0xffffffffu, sum, o);
        float inv = 1.f / sum;
        for (int j = lane; j < NWIN; j += 32) sc[r * 197 + j] *= inv;
    }
    __syncthreads();

    float acc[8];
    #pragma unroll
    for (int i = 0; i < 8; ++i) acc[i] = 0.f;
    int d0 = kg * 8;
    for (int kj = 0; kj < NWIN; ++kj) {
        float s = sc[qi * 197 + kj];
        #pragma unroll
        for (int i = 0; i < 8; ++i) acc[i] = fmaf(s, sv[kj * HD + d0 + i], acc[i]);
    }
    int y = by0 + (qi >> 3), x = bx0 + (qi & 7);
    size_t off = ((size_t)b * PP + (size_t)y * WW + x) * CC + head * HD + d0;
    float4 xv0 = *(const float4*)(xT + off);
    float4 xv1 = *(const float4*)(xT + off + 4);
    float4 gv0 = *(const float4*)(gamma1 + head * HD + d0);
    float4 gv1 = *(const float4*)(gamma1 + head * HD + d0 + 4);
    float4 o0, o1;
    o0.x = xv0.x + gv0.x * acc[0];
    o0.y = xv0.y + gv0.y * acc[1];
    o0.z = xv0.z + gv0.z * acc[2];
    o0.w = xv0.w + gv0.w * acc[3];
    o1.x = xv1.x + gv1.x * acc[4];
    o1.y = xv1.y + gv1.y * acc[5];
    o1.z = xv1.z + gv1.z * acc[6];
    o1.w = xv1.w + gv1.w * acc[7];
    *(float4*)(xres + off)     = o0;
    *(float4*)(xres + off + 4) = o1;
}

// ---------- final: out(NCHW) = xres + gamma2[c]*y, NHWC->NCHW transpose ----------
__global__ void k_final(const float* __restrict__ xres, const float* __restrict__ y,
                        const float* __restrict__ gamma2, float* __restrict__ out) {
    __shared__ float t[32][33];
    int b  = blockIdx.z;
    int p0 = blockIdx.x * 32;
    int c0 = blockIdx.y * 32;
    int tx = threadIdx.x, ty = threadIdx.y;
    const float* xb = xres + (size_t)b * PP * CC;
    const float* yb = y    + (size_t)b * PP * CC;
    #pragma unroll
    for (int i = 0; i < 32; i += 8) {
        int p = p0 + ty + i, c = c0 + tx;
        size_t off = (size_t)p * CC + c;
        t[ty + i][tx] = xb[off] + gamma2[c] * yb[off];
    }
    __syncthreads();
    float* ob = out + (size_t)b * CC * PP;
    #pragma unroll
    for (int i = 0; i < 32; i += 8)
        ob[(size_t)(c0 + ty + i) * PP + p0 + tx] = t[tx][ty + i];
}

// ---------------- launcher ----------------
extern "C" void kernel_launch(void* const* d_in, const int* in_sizes, int n_in,
                              void* d_out, int out_size) {
    const float* x      = (const float*)d_in[0];
    const float* g1     = (const float*)d_in[1];
    const float* b1     = (const float*)d_in[2];
    const float* w_q    = (const float*)d_in[3];
    const float* w_kv   = (const float*)d_in[4];
    const float* gamma1 = (const float*)d_in[5];
    const float* g2     = (const float*)d_in[6];
    const float* b2     = (const float*)d_in[7];
    const float* w_fc1  = (const float*)d_in[8];
    const float* b_fc1  = (const float*)d_in[9];
    const float* w_fc2  = (const float*)d_in[10];
    const float* b_fc2  = (const float*)d_in[11];
    const float* gamma2 = (const float*)d_in[12];
    float* out = (float*)d_out;

    float *big, *ln, *xres, *yb;
    cudaGetSymbolAddress((void**)&big,  g_big);
    cudaGetSymbolAddress((void**)&ln,   g_ln);
    cudaGetSymbolAddress((void**)&xres, g_xres);
    cudaGetSymbolAddress((void**)&yb,   g_y);
    float* xT = big;                     // [0, 8M)
    float* q  = big + (size_t)ELEM_XC;   // [8M, 16M)
    float* kv = big + (size_t)2*ELEM_XC; // [16M, 32M)
    float* h1 = big;                     // aliases xT|q|kv (disjoint lifetime)

    const int attnSmem = ATT_SMEM_FLOATS * (int)sizeof(float);
    cudaFuncSetAttribute(k_attn, cudaFuncAttributeMaxDynamicSharedMemorySize, attnSmem);

    dim3 tb32(32, 8);
    dim3 gT(PP / 32, CC / 32, BATCH);

    // 1) NCHW -> NHWC
    k_transpose_in<<<gT, tb32>>>(x, xT);
    // 2) ln1
    k_ln<<<NP, 128>>>(xT, g1, b1, ln);
    // 3) q = ln1 @ w_q
    k_gemm_bf16<<<dim3(CC / 128, NP / 128), 256>>>(ln, w_q, nullptr, q, NP, CC, CC, 0);
    // 4) kv = ln1 @ w_kv
    k_gemm_bf16<<<dim3(2 * CC / 128, NP / 128), 256>>>(ln, w_kv, nullptr, kv, NP, 2 * CC, CC, 0);
    // 5) halo attention + fused residual-1 (writes xres)
    k_attn<<<dim3(NB, NHEAD, BATCH), 256, attnSmem>>>(q, kv, xT, gamma1, xres);
    // 6) ln2
    k_ln<<<NP, 128>>>(xres, g2, b2, ln);
    // 7) fc1 + bias + gelu
    k_gemm_bf16<<<dim3(MLPH / 128, NP / 128), 256>>>(ln, w_fc1, b_fc1, h1, NP, MLPH, CC, 2);
    // 8) fc2 + bias
    k_gemm_bf16<<<dim3(CC / 128, NP / 128), 256>>>(h1, w_fc2, b_fc2, yb, NP, CC, MLPH, 1);
    // 9) final residual + NHWC -> NCHW
    k_final<<<gT, tb32>>>(xres, yb, gamma2, out);
}

// round 8
// speedup vs baseline: 3.1641x; 1.5562x over previous
#include <cuda_runtime.h>
#include <cuda_bf16.h>
#include <math.h>
#include <stdint.h>

// ---------------- problem constants ----------------
#define BATCH 4
#define CC    512
#define HH    64
#define WW    64
#define PP    (HH*WW)          // 4096 pixels per image
#define NP    (BATCH*PP)       // 16384 total pixels
#define NHEAD 16
#define HD    32               // head dim
#define BS    8
#define HALO  3
#define WIN   14
#define NWIN  (WIN*WIN)        // 196
#define NBW   (WW/BS)          // 8
#define NB    ((HH/BS)*(WW/BS))// 64 blocks per image
#define MLPH  2048
#define EPSLN 1e-5f

// ---------------- scratch (device globals; no allocs allowed) ----------------
// g_big (fp32 view, 32M floats = 128MB):
//   xT fp32 [0, 8M)      live step1..attn
//   q  fp32 [8M, 16M)    live stepQ..attn
//   kv fp32 [16M, 32M)   live stepKV..attn
//   h1 bf16 overlay [0, 16M floats) = 32M bf16   live fc1..fc2
#define ELEM_XC (NP*CC)
__device__ float          g_big [(size_t)NP*MLPH];
__device__ __nv_bfloat16  g_ln16[ELEM_XC];          // LN output bf16
__device__ float          g_xres[ELEM_XC];
__device__ float          g_y   [ELEM_XC];
// bf16 weights: wq @0 (256K), wkv @262144 (512K), wfc1 @786432 (1M), wfc2 @1835008 (1M)
__device__ __nv_bfloat16  g_w16 [2883584];

// ---------------- fp32 -> bf16 elementwise convert ----------------
__global__ void k_cvt_bf16(const float* __restrict__ in, __nv_bfloat16* __restrict__ out) {
    int i = blockIdx.x * blockDim.x + threadIdx.x;   // float4 index
    float4 v = ((const float4*)in)[i];
    __nv_bfloat162 p0 = __floats2bfloat162_rn(v.x, v.y);
    __nv_bfloat162 p1 = __floats2bfloat162_rn(v.z, v.w);
    uint2 o = {*(uint32_t*)&p0, *(uint32_t*)&p1};
    ((uint2*)out)[i] = o;
}

// ---------------- NCHW -> NHWC transpose ----------------
__global__ void k_transpose_in(const float* __restrict__ x, float* __restrict__ xT) {
    __shared__ float t[32][33];
    int b  = blockIdx.z;
    int p0 = blockIdx.x * 32;
    int c0 = blockIdx.y * 32;
    int tx = threadIdx.x, ty = threadIdx.y;      // 32 x 8
    const float* src = x + (size_t)b * CC * PP;
    #pragma unroll
    for (int i = 0; i < 32; i += 8)
        t[ty + i][tx] = src[(size_t)(c0 + ty + i) * PP + p0 + tx];
    __syncthreads();
    float* dst = xT + (size_t)b * PP * CC;
    #pragma unroll
    for (int i = 0; i < 32; i += 8)
        dst[(size_t)(p0 + ty + i) * CC + c0 + tx] = t[tx][ty + i];
}

// ---------------- LayerNorm (fp32 in, bf16 out) ----------------
__global__ void k_ln(const float* __restrict__ in, const float* __restrict__ g,
                     const float* __restrict__ bta, __nv_bfloat16* __restrict__ out) {
    int pix = blockIdx.x;
    int t   = threadIdx.x;     // 128 threads, 4 channels each
    const float4* row = (const float4*)(in + (size_t)pix * CC);
    float4 v = row[t];
    float s  = v.x + v.y + v.z + v.w;
    float s2 = v.x*v.x + v.y*v.y + v.z*v.z + v.w*v.w;
    #pragma unroll
    for (int o = 16; o; o >>= 1) {
        s  += __shfl_xor_sync(0xffffffffu, s,  o);
        s2 += __shfl_xor_sync(0xffffffffu, s2, o);
    }
    __shared__ float sh[4][2];
    int warp = t >> 5, lane = t & 31;
    if (lane == 0) { sh[warp][0] = s; sh[warp][1] = s2; }
    __syncthreads();
    s  = sh[0][0] + sh[1][0] + sh[2][0] + sh[3][0];
    s2 = sh[0][1] + sh[1][1] + sh[2][1] + sh[3][1];
    float mu = s * (1.0f / CC);
    float var = s2 * (1.0f / CC) - mu * mu;
    float rs = rsqrtf(var + EPSLN);
    float4 gv = ((const float4*)g)[t];
    float4 bv = ((const float4*)bta)[t];
    float o0 = (v.x - mu) * rs * gv.x + bv.x;
    float o1 = (v.y - mu) * rs * gv.y + bv.y;
    float o2 = (v.z - mu) * rs * gv.z + bv.z;
    float o3 = (v.w - mu) * rs * gv.w + bv.w;
    __nv_bfloat162 p0 = __floats2bfloat162_rn(o0, o1);
    __nv_bfloat162 p1 = __floats2bfloat162_rn(o2, o3);
    uint2 o = {*(uint32_t*)&p0, *(uint32_t*)&p1};
    ((uint2*)(out + (size_t)pix * CC))[t] = o;
}

// ---------------- bf16 TC GEMM v2: cp.async + ldmatrix ----------------
// C[M,N] = A[M,K](bf16) @ B[K,N](bf16); 128x128x32 tile; 8 warps 2x4; warp 64x32.
// epi: 0 none, 1 +bias, 2 +bias+GELU.  out_bf16: C is bf16 (else fp32).
#define ASTRIDE 40    // bf16 per A smem row (32 + 8 pad)
#define BSTRIDE 136   // bf16 per B smem row (128 + 8 pad)

__device__ __forceinline__ void mma_bf16(float* c, uint32_t a0, uint32_t a1,
                                         uint32_t a2, uint32_t a3,
                                         uint32_t b0, uint32_t b1) {
    asm volatile(
        "mma.sync.aligned.m16n8k16.row.col.f32.bf16.bf16.f32 "
        "{%0,%1,%2,%3}, {%4,%5,%6,%7}, {%8,%9}, {%0,%1,%2,%3};\n"
        : "+f"(c[0]), "+f"(c[1]), "+f"(c[2]), "+f"(c[3])
        : "r"(a0), "r"(a1), "r"(a2), "r"(a3), "r"(b0), "r"(b1));
}
__device__ __forceinline__ void cp_async16(uint32_t dst, const void* src) {
    asm volatile("cp.async.cg.shared.global [%0], [%1], 16;\n" :: "r"(dst), "l"(src));
}

__global__ void __launch_bounds__(256, 2)
k_gemm_bf16(const __nv_bfloat16* __restrict__ A, const __nv_bfloat16* __restrict__ B,
            const float* __restrict__ bias, void* __restrict__ Cout,
            int M, int N, int K, int epi, int out_bf16) {
    __shared__ __align__(16) __nv_bfloat16 As[2][128 * ASTRIDE];
    __shared__ __align__(16) __nv_bfloat16 Bs[2][32 * BSTRIDE];

    int tid = threadIdx.x;
    int bm = blockIdx.y << 7, bn = blockIdx.x << 7;

    // cp.async staging: A 512 chunks (128 rows x 4), B 512 chunks (32 rows x 16)
    auto copy_tile = [&](int buf, int k0) {
        #pragma unroll
        for (int i = 0; i < 2; ++i) {
            int c = tid + i * 256;
            int ar = c >> 2, a8 = (c & 3) * 8;
            cp_async16((uint32_t)__cvta_generic_to_shared(&As[buf][ar * ASTRIDE + a8]),
                       A + (size_t)(bm + ar) * K + k0 + a8);
            int br = c >> 4, b8 = (c & 15) * 8;
            cp_async16((uint32_t)__cvta_generic_to_shared(&Bs[buf][br * BSTRIDE + b8]),
                       B + (size_t)(k0 + br) * N + bn + b8);
        }
        asm volatile("cp.async.commit_group;\n");
    };

    copy_tile(0, 0);

    float acc[4][4][4];
    #pragma unroll
    for (int a = 0; a < 4; ++a)
        #pragma unroll
        for (int b = 0; b < 4; ++b)
            #pragma unroll
            for (int cI = 0; cI < 4; ++cI) acc[a][b][cI] = 0.f;

    int lane = tid & 31, warp = tid >> 5;
    int wm = (warp & 1) * 64;
    int wn = (warp >> 1) * 32;
    int gid = lane >> 2, tig = lane & 3;
    int lr = lane & 15, lc = lane >> 4;   // ldmatrix lane -> (row, col8)

    int nT = K >> 5;
    for (int t = 0; t < nT; ++t) {
        int cur = t & 1;
        asm volatile("cp.async.wait_group 0;\n");
        __syncthreads();
        if (t + 1 < nT) copy_tile(cur ^ 1, (t + 1) * 32);

        #pragma unroll
        for (int ks = 0; ks < 2; ++ks) {
            int kb = ks * 16;
            // B fragments: 2x ldmatrix.x4.trans covering n 0-15, 16-31 of warp tile
            uint32_t bfr[4][2];
            #pragma unroll
            for (int h = 0; h < 2; ++h) {
                uint32_t addr = (uint32_t)__cvta_generic_to_shared(
                    &Bs[cur][(kb + lr) * BSTRIDE + wn + h * 16 + lc * 8]);
                uint32_t r0, r1, r2, r3;
                asm volatile("ldmatrix.sync.aligned.m8n8.x4.trans.shared.b16 "
                             "{%0,%1,%2,%3}, [%4];\n"
                             : "=r"(r0), "=r"(r1), "=r"(r2), "=r"(r3) : "r"(addr));
                bfr[h * 2 + 0][0] = r0; bfr[h * 2 + 0][1] = r1;
                bfr[h * 2 + 1][0] = r2; bfr[h * 2 + 1][1] = r3;
            }
            // A fragments + mma
            #pragma unroll
            for (int mf = 0; mf < 4; ++mf) {
                uint32_t addr = (uint32_t)__cvta_generic_to_shared(
                    &As[cur][(wm + mf * 16 + lr) * ASTRIDE + kb + lc * 8]);
                uint32_t a0, a1, a2, a3;
                asm volatile("ldmatrix.sync.aligned.m8n8.x4.shared.b16 "
                             "{%0,%1,%2,%3}, [%4];\n"
                             : "=r"(a0), "=r"(a1), "=r"(a2), "=r"(a3) : "r"(addr));
                #pragma unroll
                for (int nf = 0; nf < 4; ++nf)
                    mma_bf16(acc[mf][nf], a0, a1, a2, a3, bfr[nf][0], bfr[nf][1]);
            }
        }
        __syncthreads();
    }

    // ---- epilogue ----
    #pragma unroll
    for (int mf = 0; mf < 4; ++mf) {
        #pragma unroll
        for (int nf = 0; nf < 4; ++nf) {
            int row0 = bm + wm + mf * 16 + gid;
            int col  = bn + wn + nf * 8 + 2 * tig;
            float v[4] = {acc[mf][nf][0], acc[mf][nf][1],
                          acc[mf][nf][2], acc[mf][nf][3]};
            if (epi >= 1) {
                float bb0 = bias[col], bb1 = bias[col + 1];
                v[0] += bb0; v[1] += bb1; v[2] += bb0; v[3] += bb1;
            }
            if (epi == 2) {
                #pragma unroll
                for (int i = 0; i < 4; ++i)
                    v[i] = 0.5f * v[i] * (1.f + erff(v[i] * 0.70710678118654752f));
            }
            if (out_bf16) {
                __nv_bfloat16* C16 = (__nv_bfloat16*)Cout;
                __nv_bfloat162 lo = __floats2bfloat162_rn(v[0], v[1]);
                __nv_bfloat162 hi = __floats2bfloat162_rn(v[2], v[3]);
                *(uint32_t*)(C16 + (size_t)row0 * N + col)       = *(uint32_t*)&lo;
                *(uint32_t*)(C16 + (size_t)(row0 + 8) * N + col) = *(uint32_t*)&hi;
            } else {
                float* C = (float*)Cout;
                float2 lo = {v[0], v[1]}, hi = {v[2], v[3]};
                *(float2*)(C + (size_t)row0 * N + col)       = lo;
                *(float2*)(C + (size_t)(row0 + 8) * N + col) = hi;
            }
        }
    }
}

// ---------------- halo attention: one CTA per (b, head, block) ----------------
#define SQ_OFF 0
#define SK_OFF (64*33)
#define SV_OFF (SK_OFF + NWIN*HD)
#define SC_OFF (SV_OFF + NWIN*HD)
#define ATT_SMEM_FLOATS (SC_OFF + 64*197)

__global__ void __launch_bounds__(256)
k_attn(const float* __restrict__ q, const float* __restrict__ kv,
       const float* __restrict__ xT, const float* __restrict__ gamma1,
       float* __restrict__ xres) {
    extern __shared__ float sm[];
    float* sq = sm + SQ_OFF;
    float* sk = sm + SK_OFF;
    float* sv = sm + SV_OFF;
    float* sc = sm + SC_OFF;

    int blk  = blockIdx.x;
    int head = blockIdx.y;
    int b    = blockIdx.z;
    int by0 = (blk / NBW) * BS;
    int bx0 = (blk % NBW) * BS;
    int tid = threadIdx.x;

    for (int idx = tid; idx < 64 * HD; idx += 256) {
        int r = idx >> 5, d = idx & 31;
        int y = by0 + (r >> 3), x = bx0 + (r & 7);
        sq[r * 33 + d] = q[((size_t)b * PP + (size_t)y * WW + x) * CC + head * HD + d];
    }
    for (int idx = tid; idx < NWIN * HD; idx += 256) {
        int r = idx >> 5, d = idx & 31;
        int y = by0 - HALO + r / WIN;
        int x = bx0 - HALO + r % WIN;
        float kk = 0.f, vv = 0.f;
        if (y >= 0 && y < HH && x >= 0 && x < WW) {
            size_t base = ((size_t)b * PP + (size_t)y * WW + x) * (2 * CC) + head * HD + d;
            kk = kv[base];
            vv = kv[base + CC];
        }
        sk[r * HD + d] = kk;
        sv[r * HD + d] = vv;
    }
    __syncthreads();

    int qi = tid & 63;
    int kg = tid >> 6;
    float qreg[HD];
    #pragma unroll
    for (int d = 0; d < HD; ++d) qreg[d] = sq[qi * 33 + d];
    const float scale = 0.1767766952966369f;
    for (int kj = kg; kj < NWIN; kj += 4) {
        float a = 0.f;
        #pragma unroll
        for (int d = 0; d < HD; ++d) a = fmaf(qreg[d], sk[kj * HD + d], a);
        sc[qi * 197 + kj] = a * scale;
    }
    __syncthreads();

    int warp = tid >> 5, lane = tid & 31;
    for (int r = warp; r < 64; r += 8) {
        float m = -1e30f;
        for (int j = lane; j < NWIN; j += 32) m = fmaxf(m, sc[r * 197 + j]);
        #pragma unroll
        for (int o = 16; o; o >>= 1) m = fmaxf(m, __shfl_xor_sync(0xffffffffu, m, o));
        float sum = 0.f;
        for (int j = lane; j < NWIN; j += 32) {
            float e = __expf(sc[r * 197 + j] - m);
            sc[r * 197 + j] = e;
            sum += e;
        }
        #pragma unroll
        for (int o = 16; o; o >>= 1) sum += __shfl_xor_sync(0xffffffffu, sum, o);
        float inv = 1.f / sum;
        for (int j = lane; j < NWIN; j += 32) sc[r * 197 + j] *= inv;
    }
    __syncthreads();

    float acc[8];
    #pragma unroll
    for (int i = 0; i < 8; ++i) acc[i] = 0.f;
    int d0 = kg * 8;
    for (int kj = 0; kj < NWIN; ++kj) {
        float s = sc[qi * 197 + kj];
        #pragma unroll
        for (int i = 0; i < 8; ++i) acc[i] = fmaf(s, sv[kj * HD + d0 + i], acc[i]);
    }
    int y = by0 + (qi >> 3), x = bx0 + (qi & 7);
    size_t off = ((size_t)b * PP + (size_t)y * WW + x) * CC + head * HD + d0;
    float4 xv0 = *(const float4*)(xT + off);
    float4 xv1 = *(const float4*)(xT + off + 4);
    float4 gv0 = *(const float4*)(gamma1 + head * HD + d0);
    float4 gv1 = *(const float4*)(gamma1 + head * HD + d0 + 4);
    float4 o0, o1;
    o0.x = xv0.x + gv0.x * acc[0];
    o0.y = xv0.y + gv0.y * acc[1];
    o0.z = xv0.z + gv0.z * acc[2];
    o0.w = xv0.w + gv0.w * acc[3];
    o1.x = xv1.x + gv1.x * acc[4];
    o1.y = xv1.y + gv1.y * acc[5];
    o1.z = xv1.z + gv1.z * acc[6];
    o1.w = xv1.w + gv1.w * acc[7];
    *(float4*)(xres + off)     = o0;
    *(float4*)(xres + off + 4) = o1;
}

// ---------- final: out(NCHW) = xres + gamma2[c]*y, NHWC->NCHW transpose ----------
__global__ void k_final(const float* __restrict__ xres, const float* __restrict__ y,
                        const float* __restrict__ gamma2, float* __restrict__ out) {
    __shared__ float t[32][33];
    int b  = blockIdx.z;
    int p0 = blockIdx.x * 32;
    int c0 = blockIdx.y * 32;
    int tx = threadIdx.x, ty = threadIdx.y;
    const float* xb = xres + (size_t)b * PP * CC;
    const float* yb = y    + (size_t)b * PP * CC;
    #pragma unroll
    for (int i = 0; i < 32; i += 8) {
        int p = p0 + ty + i, c = c0 + tx;
        size_t off = (size_t)p * CC + c;
        t[ty + i][tx] = xb[off] + gamma2[c] * yb[off];
    }
    __syncthreads();
    float* ob = out + (size_t)b * CC * PP;
    #pragma unroll
    for (int i = 0; i < 32; i += 8)
        ob[(size_t)(c0 + ty + i) * PP + p0 + tx] = t[tx][ty + i];
}

// ---------------- launcher ----------------
extern "C" void kernel_launch(void* const* d_in, const int* in_sizes, int n_in,
                              void* d_out, int out_size) {
    const float* x      = (const float*)d_in[0];
    const float* g1     = (const float*)d_in[1];
    const float* b1     = (const float*)d_in[2];
    const float* w_q    = (const float*)d_in[3];
    const float* w_kv   = (const float*)d_in[4];
    const float* gamma1 = (const float*)d_in[5];
    const float* g2     = (const float*)d_in[6];
    const float* b2     = (const float*)d_in[7];
    const float* w_fc1  = (const float*)d_in[8];
    const float* b_fc1  = (const float*)d_in[9];
    const float* w_fc2  = (const float*)d_in[10];
    const float* b_fc2  = (const float*)d_in[11];
    const float* gamma2 = (const float*)d_in[12];
    float* out = (float*)d_out;

    float *big, *xres, *yb;
    __nv_bfloat16 *ln16, *w16;
    cudaGetSymbolAddress((void**)&big,  g_big);
    cudaGetSymbolAddress((void**)&ln16, g_ln16);
    cudaGetSymbolAddress((void**)&xres, g_xres);
    cudaGetSymbolAddress((void**)&yb,   g_y);
    cudaGetSymbolAddress((void**)&w16,  g_w16);

    float* xT = big;                              // fp32 [0, 8M)
    float* q  = big + (size_t)ELEM_XC;            // fp32 [8M, 16M)
    float* kv = big + (size_t)2 * ELEM_XC;        // fp32 [16M, 32M)
    __nv_bfloat16* h1 = (__nv_bfloat16*)big;      // bf16 overlay [0, 16M floats)

    __nv_bfloat16* wq16   = w16;
    __nv_bfloat16* wkv16  = w16 + 262144;
    __nv_bfloat16* wfc116 = w16 + 786432;
    __nv_bfloat16* wfc216 = w16 + 1835008;

    const int attnSmem = ATT_SMEM_FLOATS * (int)sizeof(float);
    cudaFuncSetAttribute(k_attn, cudaFuncAttributeMaxDynamicSharedMemorySize, attnSmem);

    dim3 tb32(32, 8);
    dim3 gT(PP / 32, CC / 32, BATCH);

    // weights -> bf16
    k_cvt_bf16<<<(CC * CC / 4) / 256, 256>>>(w_q, wq16);
    k_cvt_bf16<<<(CC * 2 * CC / 4) / 256, 256>>>(w_kv, wkv16);
    k_cvt_bf16<<<(CC * MLPH / 4) / 256, 256>>>(w_fc1, wfc116);
    k_cvt_bf16<<<(MLPH * CC / 4) / 256, 256>>>(w_fc2, wfc216);

    // 1) NCHW -> NHWC
    k_transpose_in<<<gT, tb32>>>(x, xT);
    // 2) ln1 -> bf16
    k_ln<<<NP, 128>>>(xT, g1, b1, ln16);
    // 3) q = ln1 @ w_q (fp32 out)
    k_gemm_bf16<<<dim3(CC / 128, NP / 128), 256>>>(ln16, wq16, nullptr, q, NP, CC, CC, 0, 0);
    // 4) kv = ln1 @ w_kv (fp32 out)
    k_gemm_bf16<<<dim3(2 * CC / 128, NP / 128), 256>>>(ln16, wkv16, nullptr, kv, NP, 2 * CC, CC, 0, 0);
    // 5) halo attention + fused residual-1
    k_attn<<<dim3(NB, NHEAD, BATCH), 256, attnSmem>>>(q, kv, xT, gamma1, xres);
    // 6) ln2 -> bf16
    k_ln<<<NP, 128>>>(xres, g2, b2, ln16);
    // 7) fc1 + bias + gelu (bf16 out)
    k_gemm_bf16<<<dim3(MLPH / 128, NP / 128), 256>>>(ln16, wfc116, b_fc1, h1, NP, MLPH, CC, 2, 1);
    // 8) fc2 + bias (fp32 out)
    k_gemm_bf16<<<dim3(CC / 128, NP / 128), 256>>>(h1, wfc216, b_fc2, yb, NP, CC, MLPH, 1, 0);
    // 9) final residual + NHWC -> NCHW
    k_final<<<gT, tb32>>>(xres, yb, gamma2, out);
}

// round 9
// speedup vs baseline: 3.7722x; 1.1922x over previous
#include <cuda_runtime.h>
#include <cuda_bf16.h>
#include <math.h>
#include <stdint.h>

// ---------------- problem constants ----------------
#define BATCH 4
#define CC    512
#define HH    64
#define WW    64
#define PP    (HH*WW)
#define NP    (BATCH*PP)
#define NHEAD 16
#define HD    32
#define BS    8
#define HALO  3
#define WIN   14
#define NWIN  (WIN*WIN)        // 196
#define NKPAD 208              // 196 padded to 13*16
#define MLPH  2048
#define EPSLN 1e-5f

// ---------------- scratch ----------------
#define ELEM_XC (NP*CC)
__device__ float          g_big [(size_t)NP*MLPH];   // xT fp32 [0,8M) | q16 @8M | kv16 @16M ; h1 bf16 overlay [0,16M)
__device__ __nv_bfloat16  g_ln16[ELEM_XC];
__device__ float          g_xres[ELEM_XC];
__device__ float          g_y   [ELEM_XC];
__device__ __nv_bfloat16  g_w16 [2883584];

// ---------------- fp32 -> bf16 ----------------
__global__ void k_cvt_bf16(const float* __restrict__ in, __nv_bfloat16* __restrict__ out) {
    int i = blockIdx.x * blockDim.x + threadIdx.x;
    float4 v = ((const float4*)in)[i];
    __nv_bfloat162 p0 = __floats2bfloat162_rn(v.x, v.y);
    __nv_bfloat162 p1 = __floats2bfloat162_rn(v.z, v.w);
    uint2 o = {*(uint32_t*)&p0, *(uint32_t*)&p1};
    ((uint2*)out)[i] = o;
}

// ---------------- NCHW -> NHWC ----------------
__global__ void k_transpose_in(const float* __restrict__ x, float* __restrict__ xT) {
    __shared__ float t[32][33];
    int b  = blockIdx.z;
    int p0 = blockIdx.x * 32;
    int c0 = blockIdx.y * 32;
    int tx = threadIdx.x, ty = threadIdx.y;
    const float* src = x + (size_t)b * CC * PP;
    #pragma unroll
    for (int i = 0; i < 32; i += 8)
        t[ty + i][tx] = src[(size_t)(c0 + ty + i) * PP + p0 + tx];
    __syncthreads();
    float* dst = xT + (size_t)b * PP * CC;
    #pragma unroll
    for (int i = 0; i < 32; i += 8)
        dst[(size_t)(p0 + ty + i) * CC + c0 + tx] = t[tx][ty + i];
}

// ---------------- LayerNorm (fp32 in, bf16 out) ----------------
__global__ void k_ln(const float* __restrict__ in, const float* __restrict__ g,
                     const float* __restrict__ bta, __nv_bfloat16* __restrict__ out) {
    int pix = blockIdx.x;
    int t   = threadIdx.x;
    const float4* row = (const float4*)(in + (size_t)pix * CC);
    float4 v = row[t];
    float s  = v.x + v.y + v.z + v.w;
    float s2 = v.x*v.x + v.y*v.y + v.z*v.z + v.w*v.w;
    #pragma unroll
    for (int o = 16; o; o >>= 1) {
        s  += __shfl_xor_sync(0xffffffffu, s,  o);
        s2 += __shfl_xor_sync(0xffffffffu, s2, o);
    }
    __shared__ float sh[4][2];
    int warp = t >> 5, lane = t & 31;
    if (lane == 0) { sh[warp][0] = s; sh[warp][1] = s2; }
    __syncthreads();
    s  = sh[0][0] + sh[1][0] + sh[2][0] + sh[3][0];
    s2 = sh[0][1] + sh[1][1] + sh[2][1] + sh[3][1];
    float mu = s * (1.0f / CC);
    float var = s2 * (1.0f / CC) - mu * mu;
    float rs = rsqrtf(var + EPSLN);
    float4 gv = ((const float4*)g)[t];
    float4 bv = ((const float4*)bta)[t];
    float o0 = (v.x - mu) * rs * gv.x + bv.x;
    float o1 = (v.y - mu) * rs * gv.y + bv.y;
    float o2 = (v.z - mu) * rs * gv.z + bv.z;
    float o3 = (v.w - mu) * rs * gv.w + bv.w;
    __nv_bfloat162 p0 = __floats2bfloat162_rn(o0, o1);
    __nv_bfloat162 p1 = __floats2bfloat162_rn(o2, o3);
    uint2 o = {*(uint32_t*)&p0, *(uint32_t*)&p1};
    ((uint2*)(out + (size_t)pix * CC))[t] = o;
}

// ---------------- mma helpers ----------------
__device__ __forceinline__ void mma_bf16(float* c, uint32_t a0, uint32_t a1,
                                         uint32_t a2, uint32_t a3,
                                         uint32_t b0, uint32_t b1) {
    asm volatile(
        "mma.sync.aligned.m16n8k16.row.col.f32.bf16.bf16.f32 "
        "{%0,%1,%2,%3}, {%4,%5,%6,%7}, {%8,%9}, {%0,%1,%2,%3};\n"
        : "+f"(c[0]), "+f"(c[1]), "+f"(c[2]), "+f"(c[3])
        : "r"(a0), "r"(a1), "r"(a2), "r"(a3), "r"(b0), "r"(b1));
}
__device__ __forceinline__ void cp_async16(uint32_t dst, const void* src) {
    asm volatile("cp.async.cg.shared.global [%0], [%1], 16;\n" :: "r"(dst), "l"(src));
}
__device__ __forceinline__ void ldm_x4(uint32_t& a0, uint32_t& a1, uint32_t& a2,
                                       uint32_t& a3, const void* p) {
    uint32_t addr = (uint32_t)__cvta_generic_to_shared(p);
    asm volatile("ldmatrix.sync.aligned.m8n8.x4.shared.b16 {%0,%1,%2,%3}, [%4];\n"
                 : "=r"(a0), "=r"(a1), "=r"(a2), "=r"(a3) : "r"(addr));
}
__device__ __forceinline__ void ldm_x4t(uint32_t& a0, uint32_t& a1, uint32_t& a2,
                                        uint32_t& a3, const void* p) {
    uint32_t addr = (uint32_t)__cvta_generic_to_shared(p);
    asm volatile("ldmatrix.sync.aligned.m8n8.x4.trans.shared.b16 {%0,%1,%2,%3}, [%4];\n"
                 : "=r"(a0), "=r"(a1), "=r"(a2), "=r"(a3) : "r"(addr));
}
__device__ __forceinline__ void ldm_x2(uint32_t& b0, uint32_t& b1, const void* p) {
    uint32_t addr = (uint32_t)__cvta_generic_to_shared(p);
    asm volatile("ldmatrix.sync.aligned.m8n8.x2.shared.b16 {%0,%1}, [%2];\n"
                 : "=r"(b0), "=r"(b1) : "r"(addr));
}

// ---------------- bf16 TC GEMM: cp.async + ldmatrix ----------------
#define ASTRIDE 40
#define BSTRIDE 136

__global__ void __launch_bounds__(256, 2)
k_gemm_bf16(const __nv_bfloat16* __restrict__ A, const __nv_bfloat16* __restrict__ B,
            const float* __restrict__ bias, void* __restrict__ Cout,
            int M, int N, int K, int epi, int out_bf16) {
    __shared__ __align__(16) __nv_bfloat16 As[2][128 * ASTRIDE];
    __shared__ __align__(16) __nv_bfloat16 Bs[2][32 * BSTRIDE];

    int tid = threadIdx.x;
    int bm = blockIdx.y << 7, bn = blockIdx.x << 7;

    auto copy_tile = [&](int buf, int k0) {
        #pragma unroll
        for (int i = 0; i < 2; ++i) {
            int c = tid + i * 256;
            int ar = c >> 2, a8 = (c & 3) * 8;
            cp_async16((uint32_t)__cvta_generic_to_shared(&As[buf][ar * ASTRIDE + a8]),
                       A + (size_t)(bm + ar) * K + k0 + a8);
            int br = c >> 4, b8 = (c & 15) * 8;
            cp_async16((uint32_t)__cvta_generic_to_shared(&Bs[buf][br * BSTRIDE + b8]),
                       B + (size_t)(k0 + br) * N + bn + b8);
        }
        asm volatile("cp.async.commit_group;\n");
    };

    copy_tile(0, 0);

    float acc[4][4][4];
    #pragma unroll
    for (int a = 0; a < 4; ++a)
        #pragma unroll
        for (int b = 0; b < 4; ++b)
            #pragma unroll
            for (int cI = 0; cI < 4; ++cI) acc[a][b][cI] = 0.f;

    int lane = tid & 31, warp = tid >> 5;
    int wm = (warp & 1) * 64;
    int wn = (warp >> 1) * 32;
    int gid = lane >> 2, tig = lane & 3;
    int lr = lane & 15, lc = lane >> 4;

    int nT = K >> 5;
    for (int t = 0; t < nT; ++t) {
        int cur = t & 1;
        asm volatile("cp.async.wait_group 0;\n");
        __syncthreads();
        if (t + 1 < nT) copy_tile(cur ^ 1, (t + 1) * 32);

        #pragma unroll
        for (int ks = 0; ks < 2; ++ks) {
            int kb = ks * 16;
            uint32_t bfr[4][2];
            #pragma unroll
            for (int h = 0; h < 2; ++h) {
                uint32_t r0, r1, r2, r3;
                ldm_x4t(r0, r1, r2, r3, &Bs[cur][(kb + lr) * BSTRIDE + wn + h * 16 + lc * 8]);
                bfr[h * 2 + 0][0] = r0; bfr[h * 2 + 0][1] = r1;
                bfr[h * 2 + 1][0] = r2; bfr[h * 2 + 1][1] = r3;
            }
            #pragma unroll
            for (int mf = 0; mf < 4; ++mf) {
                uint32_t a0, a1, a2, a3;
                ldm_x4(a0, a1, a2, a3, &As[cur][(wm + mf * 16 + lr) * ASTRIDE + kb + lc * 8]);
                #pragma unroll
                for (int nf = 0; nf < 4; ++nf)
                    mma_bf16(acc[mf][nf], a0, a1, a2, a3, bfr[nf][0], bfr[nf][1]);
            }
        }
        __syncthreads();
    }

    #pragma unroll
    for (int mf = 0; mf < 4; ++mf) {
        #pragma unroll
        for (int nf = 0; nf < 4; ++nf) {
            int row0 = bm + wm + mf * 16 + gid;
            int col  = bn + wn + nf * 8 + 2 * tig;
            float v[4] = {acc[mf][nf][0], acc[mf][nf][1],
                          acc[mf][nf][2], acc[mf][nf][3]};
            if (epi >= 1) {
                float bb0 = bias[col], bb1 = bias[col + 1];
                v[0] += bb0; v[1] += bb1; v[2] += bb0; v[3] += bb1;
            }
            if (epi == 2) {
                #pragma unroll
                for (int i = 0; i < 4; ++i)
                    v[i] = 0.5f * v[i] * (1.f + erff(v[i] * 0.70710678118654752f));
            }
            if (out_bf16) {
                __nv_bfloat16* C16 = (__nv_bfloat16*)Cout;
                __nv_bfloat162 lo = __floats2bfloat162_rn(v[0], v[1]);
                __nv_bfloat162 hi = __floats2bfloat162_rn(v[2], v[3]);
                *(uint32_t*)(C16 + (size_t)row0 * N + col)       = *(uint32_t*)&lo;
                *(uint32_t*)(C16 + (size_t)(row0 + 8) * N + col) = *(uint32_t*)&hi;
            } else {
                float* C = (float*)Cout;
                float2 lo = {v[0], v[1]}, hi = {v[2], v[3]};
                *(float2*)(C + (size_t)row0 * N + col)       = lo;
                *(float2*)(C + (size_t)(row0 + 8) * N + col) = hi;
            }
        }
    }
}

// ---------------- tensor-core halo attention ----------------
// smem bytes: sq 0..5120 | sk 5120..21760 | sv 21760..38400 | S(f32) 38400..93696 | P(bf16) 93696..121344
#define ATT_SMEM_BYTES 121344
#define SSTR 216   // S/P row stride (elements)

__global__ void __launch_bounds__(256)
k_attn(const __nv_bfloat16* __restrict__ q, const __nv_bfloat16* __restrict__ kv,
       const float* __restrict__ xT, const float* __restrict__ gamma1,
       float* __restrict__ xres) {
    extern __shared__ char smem[];
    __nv_bfloat16* sq = (__nv_bfloat16*)smem;
    __nv_bfloat16* sk = (__nv_bfloat16*)(smem + 5120);
    __nv_bfloat16* sv = (__nv_bfloat16*)(smem + 21760);
    float*         ss = (float*)        (smem + 38400);
    __nv_bfloat16* sp = (__nv_bfloat16*)(smem + 93696);

    int blk = blockIdx.x, head = blockIdx.y, b = blockIdx.z;
    int by0 = (blk >> 3) * BS, bx0 = (blk & 7) * BS;
    int tid = threadIdx.x;
    int lane = tid & 31, warp = tid >> 5;

    // q tile 64x32 bf16: one uint4 (8 bf16) per thread
    {
        int r = tid >> 2, d8 = (tid & 3) * 8;
        int y = by0 + (r >> 3), x = bx0 + (r & 7);
        *(uint4*)&sq[r * 40 + d8] =
            *(const uint4*)(q + ((size_t)b * PP + (size_t)y * WW + x) * CC + head * HD + d8);
    }
    // k/v window 208x32 (rows >=196 zero, OOB zero)
    for (int c = tid; c < NKPAD * 4; c += 256) {
        int r = c >> 2, d8 = (c & 3) * 8;
        int y = by0 - HALO + r / WIN;
        int x = bx0 - HALO + r % WIN;
        uint4 kk = {0,0,0,0}, vv = {0,0,0,0};
        if (r < NWIN && y >= 0 && y < HH && x >= 0 && x < WW) {
            size_t base = ((size_t)b * PP + (size_t)y * WW + x) * (2 * CC) + head * HD + d8;
            kk = *(const uint4*)(kv + base);
            vv = *(const uint4*)(kv + base + CC);
        }
        *(uint4*)&sk[r * 40 + d8] = kk;
        *(uint4*)&sv[r * 40 + d8] = vv;
    }
    __syncthreads();

    int mw = warp & 3, nh = warp >> 2;     // m-frag 0-3, n-half 0-1
    int lr = lane & 15, lc = lane >> 4;
    int gid = lane >> 2, tig = lane & 3;
    int r2 = lane & 7, sel = (lane >> 3) & 1;

    // ---- S = Q K^T (64 x 208) ----
    {
        float accS[13][4];
        #pragma unroll
        for (int nf = 0; nf < 13; ++nf)
            #pragma unroll
            for (int i = 0; i < 4; ++i) accS[nf][i] = 0.f;
        #pragma unroll
        for (int ks = 0; ks < 2; ++ks) {
            uint32_t a0, a1, a2, a3;
            ldm_x4(a0, a1, a2, a3, &sq[(mw * 16 + lr) * 40 + ks * 16 + lc * 8]);
            #pragma unroll
            for (int nf = 0; nf < 13; ++nf) {
                int n0 = (nh * 13 + nf) * 8;
                uint32_t b0, b1;
                ldm_x2(b0, b1, &sk[(n0 + r2) * 40 + ks * 16 + sel * 8]);
                mma_bf16(accS[nf], a0, a1, a2, a3, b0, b1);
            }
        }
        #pragma unroll
        for (int nf = 0; nf < 13; ++nf) {
            int col = (nh * 13 + nf) * 8 + 2 * tig;
            int row = mw * 16 + gid;
            float2 lo = {accS[nf][0], accS[nf][1]};
            float2 hi = {accS[nf][2], accS[nf][3]};
            *(float2*)&ss[row * SSTR + col]       = lo;
            *(float2*)&ss[(row + 8) * SSTR + col] = hi;
        }
    }
    __syncthreads();

    // ---- softmax rows (scale fused), P -> bf16, pad cols zeroed ----
    const float scale = 0.1767766952966369f;  // 1/sqrt(32)
    for (int r = warp; r < 64; r += 8) {
        float mx = -1e30f;
        for (int j = lane; j < NWIN; j += 32) mx = fmaxf(mx, ss[r * SSTR + j]);
        #pragma unroll
        for (int o = 16; o; o >>= 1) mx = fmaxf(mx, __shfl_xor_sync(0xffffffffu, mx, o));
        mx *= scale;
        float sum = 0.f;
        for (int j = lane; j < NWIN; j += 32) {
            float e = __expf(ss[r * SSTR + j] * scale - mx);
            ss[r * SSTR + j] = e;
            sum += e;
        }
        #pragma unroll
        for (int o = 16; o; o >>= 1) sum += __shfl_xor_sync(0xffffffffu, sum, o);
        float inv = 1.f / sum;
        for (int j = lane; j < NWIN; j += 32)
            sp[r * SSTR + j] = __float2bfloat16(ss[r * SSTR + j] * inv);
        if (lane < SSTR - NWIN) sp[r * SSTR + NWIN + lane] = __float2bfloat16(0.f);
    }
    __syncthreads();

    // ---- O = P V (64 x 32), fused gamma1-residual ----
    float acc[2][4];
    #pragma unroll
    for (int i = 0; i < 2; ++i)
        #pragma unroll
        for (int j = 0; j < 4; ++j) acc[i][j] = 0.f;

    #pragma unroll
    for (int ks = 0; ks < 13; ++ks) {
        uint32_t a0, a1, a2, a3;
        ldm_x4(a0, a1, a2, a3, &sp[(mw * 16 + lr) * SSTR + ks * 16 + lc * 8]);
        uint32_t v0, v1, v2, v3;
        ldm_x4t(v0, v1, v2, v3, &sv[(ks * 16 + lr) * 40 + nh * 16 + lc * 8]);
        mma_bf16(acc[0], a0, a1, a2, a3, v0, v1);
        mma_bf16(acc[1], a0, a1, a2, a3, v2, v3);
    }

    #pragma unroll
    for (int nfl = 0; nfl < 2; ++nfl) {
        int col = nh * 16 + nfl * 8 + 2 * tig;       // d 0..31
        float2 gv = *(const float2*)(gamma1 + head * HD + col);
        #pragma unroll
        for (int h = 0; h < 2; ++h) {
            int qi = mw * 16 + gid + h * 8;
            int y = by0 + (qi >> 3), x = bx0 + (qi & 7);
            size_t off = ((size_t)b * PP + (size_t)y * WW + x) * CC + head * HD + col;
            float2 xv = *(const float2*)(xT + off);
            float2 o;
            o.x = xv.x + gv.x * acc[nfl][h * 2 + 0];
            o.y = xv.y + gv.y * acc[nfl][h * 2 + 1];
            *(float2*)(xres + off) = o;
        }
    }
}

// ---------- final: out(NCHW) = xres + gamma2[c]*y ----------
__global__ void k_final(const float* __restrict__ xres, const float* __restrict__ y,
                        const float* __restrict__ gamma2, float* __restrict__ out) {
    __shared__ float t[32][33];
    int b  = blockIdx.z;
    int p0 = blockIdx.x * 32;
    int c0 = blockIdx.y * 32;
    int tx = threadIdx.x, ty = threadIdx.y;
    const float* xb = xres + (size_t)b * PP * CC;
    const float* yb = y    + (size_t)b * PP * CC;
    #pragma unroll
    for (int i = 0; i < 32; i += 8) {
        int p = p0 + ty + i, c = c0 + tx;
        size_t off = (size_t)p * CC + c;
        t[ty + i][tx] = xb[off] + gamma2[c] * yb[off];
    }
    __syncthreads();
    float* ob = out + (size_t)b * CC * PP;
    #pragma unroll
    for (int i = 0; i < 32; i += 8)
        ob[(size_t)(c0 + ty + i) * PP + p0 + tx] = t[tx][ty + i];
}

// ---------------- launcher ----------------
extern "C" void kernel_launch(void* const* d_in, const int* in_sizes, int n_in,
                              void* d_out, int out_size) {
    const float* x      = (const float*)d_in[0];
    const float* g1     = (const float*)d_in[1];
    const float* b1     = (const float*)d_in[2];
    const float* w_q    = (const float*)d_in[3];
    const float* w_kv   = (const float*)d_in[4];
    const float* gamma1 = (const float*)d_in[5];
    const float* g2     = (const float*)d_in[6];
    const float* b2     = (const float*)d_in[7];
    const float* w_fc1  = (const float*)d_in[8];
    const float* b_fc1  = (const float*)d_in[9];
    const float* w_fc2  = (const float*)d_in[10];
    const float* b_fc2  = (const float*)d_in[11];
    const float* gamma2 = (const float*)d_in[12];
    float* out = (float*)d_out;

    float *big, *xres, *yb;
    __nv_bfloat16 *ln16, *w16;
    cudaGetSymbolAddress((void**)&big,  g_big);
    cudaGetSymbolAddress((void**)&ln16, g_ln16);
    cudaGetSymbolAddress((void**)&xres, g_xres);
    cudaGetSymbolAddress((void**)&yb,   g_y);
    cudaGetSymbolAddress((void**)&w16,  g_w16);

    float* xT = big;                                       // fp32 [0, 8M)
    __nv_bfloat16* q16  = (__nv_bfloat16*)(big + (size_t)ELEM_XC);      // bf16 @8M floats
    __nv_bfloat16* kv16 = (__nv_bfloat16*)(big + (size_t)2 * ELEM_XC);  // bf16 @16M floats
    __nv_bfloat16* h1 = (__nv_bfloat16*)big;               // bf16 overlay [0, 16M floats)

    __nv_bfloat16* wq16   = w16;
    __nv_bfloat16* wkv16  = w16 + 262144;
    __nv_bfloat16* wfc116 = w16 + 786432;
    __nv_bfloat16* wfc216 = w16 + 1835008;

    cudaFuncSetAttribute(k_attn, cudaFuncAttributeMaxDynamicSharedMemorySize, ATT_SMEM_BYTES);

    dim3 tb32(32, 8);
    dim3 gT(PP / 32, CC / 32, BATCH);

    // weights -> bf16
    k_cvt_bf16<<<(CC * CC / 4) / 256, 256>>>(w_q, wq16);
    k_cvt_bf16<<<(CC * 2 * CC / 4) / 256, 256>>>(w_kv, wkv16);
    k_cvt_bf16<<<(CC * MLPH / 4) / 256, 256>>>(w_fc1, wfc116);
    k_cvt_bf16<<<(MLPH * CC / 4) / 256, 256>>>(w_fc2, wfc216);

    // 1) NCHW -> NHWC
    k_transpose_in<<<gT, tb32>>>(x, xT);
    // 2) ln1 -> bf16
    k_ln<<<NP, 128>>>(xT, g1, b1, ln16);
    // 3) q = ln1 @ w_q (bf16 out)
    k_gemm_bf16<<<dim3(CC / 128, NP / 128), 256>>>(ln16, wq16, nullptr, q16, NP, CC, CC, 0, 1);
    // 4) kv = ln1 @ w_kv (bf16 out)
    k_gemm_bf16<<<dim3(2 * CC / 128, NP / 128), 256>>>(ln16, wkv16, nullptr, kv16, NP, 2 * CC, CC, 0, 1);
    // 5) tensor-core halo attention + fused residual-1
    k_attn<<<dim3(64, NHEAD, BATCH), 256, ATT_SMEM_BYTES>>>(q16, kv16, xT, gamma1, xres);
    // 6) ln2 -> bf16
    k_ln<<<NP, 128>>>(xres, g2, b2, ln16);
    // 7) fc1 + bias + gelu (bf16 out)
    k_gemm_bf16<<<dim3(MLPH / 128, NP / 128), 256>>>(ln16, wfc116, b_fc1, h1, NP, MLPH, CC, 2, 1);
    // 8) fc2 + bias (fp32 out)
    k_gemm_bf16<<<dim3(CC / 128, NP / 128), 256>>>(h1, wfc216, b_fc2, yb, NP, CC, MLPH, 1, 0);
    // 9) final residual + NHWC -> NCHW
    k_final<<<gT, tb32>>>(xres, yb, gamma2, out);
}

// round 10
// speedup vs baseline: 3.8222x; 1.0132x over previous
#include <cuda_runtime.h>
#include <cuda_bf16.h>
#include <math.h>
#include <stdint.h>

// ---------------- problem constants ----------------
#define BATCH 4
#define CC    512
#define HH    64
#define WW    64
#define PP    (HH*WW)
#define NP    (BATCH*PP)
#define NHEAD 16
#define HD    32
#define BS    8
#define HALO  3
#define WIN   14
#define NWIN  (WIN*WIN)        // 196
#define NKPAD 208
#define MLPH  2048
#define EPSLN 1e-5f
#define QKVS  1536             // combined qkv row stride

// ---------------- scratch ----------------
#define ELEM_XC (NP*CC)
__device__ float          g_big [(size_t)NP*MLPH];   // xT fp32 [0,8M) | qkv16 @8M..20M ; h1 bf16 overlay [0,16M)
__device__ __nv_bfloat16  g_ln16[ELEM_XC];
__device__ float          g_xres[ELEM_XC];
__device__ float          g_y   [ELEM_XC];
// wqkv16 @0 (786432 = 512*1536), wfc1 @786432 (1M), wfc2 @1835008 (1M)
__device__ __nv_bfloat16  g_w16 [2883584];

// ---------------- strided fp32 -> bf16 convert (uint2 = 4 bf16 chunks) ----------------
__global__ void k_cvt_str(const float* __restrict__ in, uint2* __restrict__ out,
                          int cols4, int ostride4, int ooff4) {
    int i = blockIdx.x * blockDim.x + threadIdx.x;
    float4 v = ((const float4*)in)[i];
    __nv_bfloat162 p0 = __floats2bfloat162_rn(v.x, v.y);
    __nv_bfloat162 p1 = __floats2bfloat162_rn(v.z, v.w);
    uint2 o = {*(uint32_t*)&p0, *(uint32_t*)&p1};
    int k = i / cols4, c = i % cols4;
    out[k * ostride4 + ooff4 + c] = o;
}

// ---------------- fused NCHW->NHWC transpose + LayerNorm1 ----------------
// CTA: 32 pixels; smem [32][521] fp32. Writes xT (fp32 NHWC) and ln16 (bf16 NHWC).
#define TLN_SMEM (32*521*4)
__global__ void __launch_bounds__(256)
k_tln(const float* __restrict__ x, const float* __restrict__ g,
      const float* __restrict__ bta, float* __restrict__ xT,
      __nv_bfloat16* __restrict__ ln16) {
    extern __shared__ float s[];   // [32][521]
    int b = blockIdx.y, p0 = blockIdx.x * 32;
    int tid = threadIdx.x;
    const float* xb = x + (size_t)b * CC * PP + p0;
    #pragma unroll
    for (int it = 0; it < 64; ++it) {
        int idx = it * 256 + tid;
        int c = idx >> 5, tp = idx & 31;
        s[tp * 521 + c] = xb[(size_t)c * PP + tp];
    }
    __syncthreads();
    int warp = tid >> 5, lane = tid & 31;
    for (int pi = warp; pi < 32; pi += 8) {
        float sum = 0.f, sq = 0.f;
        #pragma unroll
        for (int j = 0; j < 16; ++j) {
            float v = s[pi * 521 + lane + 32 * j];
            sum += v; sq += v * v;
        }
        #pragma unroll
        for (int o = 16; o; o >>= 1) {
            sum += __shfl_xor_sync(0xffffffffu, sum, o);
            sq  += __shfl_xor_sync(0xffffffffu, sq,  o);
        }
        float mu = sum * (1.0f / CC);
        float rs = rsqrtf(sq * (1.0f / CC) - mu * mu + EPSLN);
        size_t orow = ((size_t)b * PP + p0 + pi) * CC;
        #pragma unroll
        for (int j = 0; j < 4; ++j) {
            int c = lane * 4 + j * 128;
            float4 gv = *(const float4*)(g + c);
            float4 bv = *(const float4*)(bta + c);
            float v0 = s[pi * 521 + c + 0], v1 = s[pi * 521 + c + 1];
            float v2 = s[pi * 521 + c + 2], v3 = s[pi * 521 + c + 3];
            float4 o4 = {v0, v1, v2, v3};
            *(float4*)(xT + orow + c) = o4;
            float l0 = (v0 - mu) * rs * gv.x + bv.x;
            float l1 = (v1 - mu) * rs * gv.y + bv.y;
            float l2 = (v2 - mu) * rs * gv.z + bv.z;
            float l3 = (v3 - mu) * rs * gv.w + bv.w;
            __nv_bfloat162 q0 = __floats2bfloat162_rn(l0, l1);
            __nv_bfloat162 q1 = __floats2bfloat162_rn(l2, l3);
            uint2 pk = {*(uint32_t*)&q0, *(uint32_t*)&q1};
            *(uint2*)(ln16 + orow + c) = pk;
        }
    }
}

// ---------------- LayerNorm (fp32 in, bf16 out) -- used for ln2 ----------------
__global__ void k_ln(const float* __restrict__ in, const float* __restrict__ g,
                     const float* __restrict__ bta, __nv_bfloat16* __restrict__ out) {
    int pix = blockIdx.x;
    int t   = threadIdx.x;
    const float4* row = (const float4*)(in + (size_t)pix * CC);
    float4 v = row[t];
    float s  = v.x + v.y + v.z + v.w;
    float s2 = v.x*v.x + v.y*v.y + v.z*v.z + v.w*v.w;
    #pragma unroll
    for (int o = 16; o; o >>= 1) {
        s  += __shfl_xor_sync(0xffffffffu, s,  o);
        s2 += __shfl_xor_sync(0xffffffffu, s2, o);
    }
    __shared__ float sh[4][2];
    int warp = t >> 5, lane = t & 31;
    if (lane == 0) { sh[warp][0] = s; sh[warp][1] = s2; }
    __syncthreads();
    s  = sh[0][0] + sh[1][0] + sh[2][0] + sh[3][0];
    s2 = sh[0][1] + sh[1][1] + sh[2][1] + sh[3][1];
    float mu = s * (1.0f / CC);
    float var = s2 * (1.0f / CC) - mu * mu;
    float rs = rsqrtf(var + EPSLN);
    float4 gv = ((const float4*)g)[t];
    float4 bv = ((const float4*)bta)[t];
    float o0 = (v.x - mu) * rs * gv.x + bv.x;
    float o1 = (v.y - mu) * rs * gv.y + bv.y;
    float o2 = (v.z - mu) * rs * gv.z + bv.z;
    float o3 = (v.w - mu) * rs * gv.w + bv.w;
    __nv_bfloat162 p0 = __floats2bfloat162_rn(o0, o1);
    __nv_bfloat162 p1 = __floats2bfloat162_rn(o2, o3);
    uint2 o = {*(uint32_t*)&p0, *(uint32_t*)&p1};
    ((uint2*)(out + (size_t)pix * CC))[t] = o;
}

// ---------------- mma helpers ----------------
__device__ __forceinline__ void mma_bf16(float* c, uint32_t a0, uint32_t a1,
                                         uint32_t a2, uint32_t a3,
                                         uint32_t b0, uint32_t b1) {
    asm volatile(
        "mma.sync.aligned.m16n8k16.row.col.f32.bf16.bf16.f32 "
        "{%0,%1,%2,%3}, {%4,%5,%6,%7}, {%8,%9}, {%0,%1,%2,%3};\n"
        : "+f"(c[0]), "+f"(c[1]), "+f"(c[2]), "+f"(c[3])
        : "r"(a0), "r"(a1), "r"(a2), "r"(a3), "r"(b0), "r"(b1));
}
__device__ __forceinline__ void cp_async16(uint32_t dst, const void* src) {
    asm volatile("cp.async.cg.shared.global [%0], [%1], 16;\n" :: "r"(dst), "l"(src));
}
__device__ __forceinline__ void ldm_x4(uint32_t& a0, uint32_t& a1, uint32_t& a2,
                                       uint32_t& a3, const void* p) {
    uint32_t addr = (uint32_t)__cvta_generic_to_shared(p);
    asm volatile("ldmatrix.sync.aligned.m8n8.x4.shared.b16 {%0,%1,%2,%3}, [%4];\n"
                 : "=r"(a0), "=r"(a1), "=r"(a2), "=r"(a3) : "r"(addr));
}
__device__ __forceinline__ void ldm_x4t(uint32_t& a0, uint32_t& a1, uint32_t& a2,
                                        uint32_t& a3, const void* p) {
    uint32_t addr = (uint32_t)__cvta_generic_to_shared(p);
    asm volatile("ldmatrix.sync.aligned.m8n8.x4.trans.shared.b16 {%0,%1,%2,%3}, [%4];\n"
                 : "=r"(a0), "=r"(a1), "=r"(a2), "=r"(a3) : "r"(addr));
}
__device__ __forceinline__ void ldm_x2(uint32_t& b0, uint32_t& b1, const void* p) {
    uint32_t addr = (uint32_t)__cvta_generic_to_shared(p);
    asm volatile("ldmatrix.sync.aligned.m8n8.x2.shared.b16 {%0,%1}, [%2];\n"
                 : "=r"(b0), "=r"(b1) : "r"(addr));
}

// ---------------- bf16 TC GEMM: 3-stage cp.async + ldmatrix ----------------
#define ASTRIDE 40
#define BSTRIDE 136
#define GEMM_SMEM ((3*128*ASTRIDE + 3*32*BSTRIDE) * 2)   // 56832 bytes

__global__ void __launch_bounds__(256, 2)
k_gemm_bf16(const __nv_bfloat16* __restrict__ A, const __nv_bfloat16* __restrict__ B,
            const float* __restrict__ bias, void* __restrict__ Cout,
            int M, int N, int K, int epi, int out_bf16) {
    extern __shared__ __align__(16) __nv_bfloat16 dsm[];
    __nv_bfloat16* Asm = dsm;                       // 3 x 128*ASTRIDE
    __nv_bfloat16* Bsm = dsm + 3 * 128 * ASTRIDE;   // 3 x 32*BSTRIDE

    int tid = threadIdx.x;
    int bm = blockIdx.y << 7, bn = blockIdx.x << 7;

    auto copy_tile = [&](int buf, int k0) {
        __nv_bfloat16* Ab = Asm + buf * 128 * ASTRIDE;
        __nv_bfloat16* Bb = Bsm + buf * 32 * BSTRIDE;
        #pragma unroll
        for (int i = 0; i < 2; ++i) {
            int c = tid + i * 256;
            int ar = c >> 2, a8 = (c & 3) * 8;
            cp_async16((uint32_t)__cvta_generic_to_shared(&Ab[ar * ASTRIDE + a8]),
                       A + (size_t)(bm + ar) * K + k0 + a8);
            int br = c >> 4, b8 = (c & 15) * 8;
            cp_async16((uint32_t)__cvta_generic_to_shared(&Bb[br * BSTRIDE + b8]),
                       B + (size_t)(k0 + br) * N + bn + b8);
        }
        asm volatile("cp.async.commit_group;\n");
    };

    int nT = K >> 5;
    copy_tile(0, 0);
    copy_tile(1, 32);      // nT >= 2 always (K >= 64)

    float acc[4][4][4];
    #pragma unroll
    for (int a = 0; a < 4; ++a)
        #pragma unroll
        for (int b = 0; b < 4; ++b)
            #pragma unroll
            for (int cI = 0; cI < 4; ++cI) acc[a][b][cI] = 0.f;

    int lane = tid & 31, warp = tid >> 5;
    int wm = (warp & 1) * 64;
    int wn = (warp >> 1) * 32;
    int gid = lane >> 2, tig = lane & 3;
    int lr = lane & 15, lc = lane >> 4;

    int cur = 0;
    for (int t = 0; t < nT; ++t) {
        if (t + 1 < nT) { asm volatile("cp.async.wait_group 1;\n"); }
        else            { asm volatile("cp.async.wait_group 0;\n"); }
        __syncthreads();
        if (t + 2 < nT) {
            int nb = cur + 2; if (nb >= 3) nb -= 3;
            copy_tile(nb, (t + 2) * 32);
        }
        __nv_bfloat16* Ab = Asm + cur * 128 * ASTRIDE;
        __nv_bfloat16* Bb = Bsm + cur * 32 * BSTRIDE;

        #pragma unroll
        for (int ks = 0; ks < 2; ++ks) {
            int kb = ks * 16;
            uint32_t bfr[4][2];
            #pragma unroll
            for (int h = 0; h < 2; ++h) {
                uint32_t r0, r1, r2, r3;
                ldm_x4t(r0, r1, r2, r3, &Bb[(kb + lr) * BSTRIDE + wn + h * 16 + lc * 8]);
                bfr[h * 2 + 0][0] = r0; bfr[h * 2 + 0][1] = r1;
                bfr[h * 2 + 1][0] = r2; bfr[h * 2 + 1][1] = r3;
            }
            #pragma unroll
            for (int mf = 0; mf < 4; ++mf) {
                uint32_t a0, a1, a2, a3;
                ldm_x4(a0, a1, a2, a3, &Ab[(wm + mf * 16 + lr) * ASTRIDE + kb + lc * 8]);
                #pragma unroll
                for (int nf = 0; nf < 4; ++nf)
                    mma_bf16(acc[mf][nf], a0, a1, a2, a3, bfr[nf][0], bfr[nf][1]);
            }
        }
        if (++cur == 3) cur = 0;
    }

    #pragma unroll
    for (int mf = 0; mf < 4; ++mf) {
        #pragma unroll
        for (int nf = 0; nf < 4; ++nf) {
            int row0 = bm + wm + mf * 16 + gid;
            int col  = bn + wn + nf * 8 + 2 * tig;
            float v[4] = {acc[mf][nf][0], acc[mf][nf][1],
                          acc[mf][nf][2], acc[mf][nf][3]};
            if (epi >= 1) {
                float bb0 = bias[col], bb1 = bias[col + 1];
                v[0] += bb0; v[1] += bb1; v[2] += bb0; v[3] += bb1;
            }
            if (epi == 2) {
                #pragma unroll
                for (int i = 0; i < 4; ++i)
                    v[i] = 0.5f * v[i] * (1.f + erff(v[i] * 0.70710678118654752f));
            }
            if (out_bf16) {
                __nv_bfloat16* C16 = (__nv_bfloat16*)Cout;
                __nv_bfloat162 lo = __floats2bfloat162_rn(v[0], v[1]);
                __nv_bfloat162 hi = __floats2bfloat162_rn(v[2], v[3]);
                *(uint32_t*)(C16 + (size_t)row0 * N + col)       = *(uint32_t*)&lo;
                *(uint32_t*)(C16 + (size_t)(row0 + 8) * N + col) = *(uint32_t*)&hi;
            } else {
                float* C = (float*)Cout;
                float2 lo = {v[0], v[1]}, hi = {v[2], v[3]};
                *(float2*)(C + (size_t)row0 * N + col)       = lo;
                *(float2*)(C + (size_t)(row0 + 8) * N + col) = hi;
            }
        }
    }
}

// ---------------- tensor-core halo attention (combined qkv input) ----------------
#define ATT_SMEM_BYTES 121344
#define SSTR 216

__global__ void __launch_bounds__(256)
k_attn(const __nv_bfloat16* __restrict__ qkv, const float* __restrict__ xT,
       const float* __restrict__ gamma1, float* __restrict__ xres) {
    extern __shared__ char smem[];
    __nv_bfloat16* sq = (__nv_bfloat16*)smem;
    __nv_bfloat16* sk = (__nv_bfloat16*)(smem + 5120);
    __nv_bfloat16* sv = (__nv_bfloat16*)(smem + 21760);
    float*         ss = (float*)        (smem + 38400);
    __nv_bfloat16* sp = (__nv_bfloat16*)(smem + 93696);

    int blk = blockIdx.x, head = blockIdx.y, b = blockIdx.z;
    int by0 = (blk >> 3) * BS, bx0 = (blk & 7) * BS;
    int tid = threadIdx.x;
    int lane = tid & 31, warp = tid >> 5;

    {
        int r = tid >> 2, d8 = (tid & 3) * 8;
        int y = by0 + (r >> 3), x = bx0 + (r & 7);
        *(uint4*)&sq[r * 40 + d8] =
            *(const uint4*)(qkv + ((size_t)b * PP + (size_t)y * WW + x) * QKVS + head * HD + d8);
    }
    for (int c = tid; c < NKPAD * 4; c += 256) {
        int r = c >> 2, d8 = (c & 3) * 8;
        int y = by0 - HALO + r / WIN;
        int x = bx0 - HALO + r % WIN;
        uint4 kk = {0,0,0,0}, vv = {0,0,0,0};
        if (r < NWIN && y >= 0 && y < HH && x >= 0 && x < WW) {
            const __nv_bfloat16* base =
                qkv + ((size_t)b * PP + (size_t)y * WW + x) * QKVS + CC + head * HD + d8;
            kk = *(const uint4*)base;
            vv = *(const uint4*)(base + CC);
        }
        *(uint4*)&sk[r * 40 + d8] = kk;
        *(uint4*)&sv[r * 40 + d8] = vv;
    }
    __syncthreads();

    int mw = warp & 3, nh = warp >> 2;
    int lr = lane & 15, lc = lane >> 4;
    int gid = lane >> 2, tig = lane & 3;
    int r2 = lane & 7, sel = (lane >> 3) & 1;

    {
        float accS[13][4];
        #pragma unroll
        for (int nf = 0; nf < 13; ++nf)
            #pragma unroll
            for (int i = 0; i < 4; ++i) accS[nf][i] = 0.f;
        #pragma unroll
        for (int ks = 0; ks < 2; ++ks) {
            uint32_t a0, a1, a2, a3;
            ldm_x4(a0, a1, a2, a3, &sq[(mw * 16 + lr) * 40 + ks * 16 + lc * 8]);
            #pragma unroll
            for (int nf = 0; nf < 13; ++nf) {
                int n0 = (nh * 13 + nf) * 8;
                uint32_t b0, b1;
                ldm_x2(b0, b1, &sk[(n0 + r2) * 40 + ks * 16 + sel * 8]);
                mma_bf16(accS[nf], a0, a1, a2, a3, b0, b1);
            }
        }
        #pragma unroll
        for (int nf = 0; nf < 13; ++nf) {
            int col = (nh * 13 + nf) * 8 + 2 * tig;
            int row = mw * 16 + gid;
            float2 lo = {accS[nf][0], accS[nf][1]};
            float2 hi = {accS[nf][2], accS[nf][3]};
            *(float2*)&ss[row * SSTR + col]       = lo;
            *(float2*)&ss[(row + 8) * SSTR + col] = hi;
        }
    }
    __syncthreads();

    const float scale = 0.1767766952966369f;
    for (int r = warp; r < 64; r += 8) {
        float mx = -1e30f;
        for (int j = lane; j < NWIN; j += 32) mx = fmaxf(mx, ss[r * SSTR + j]);
        #pragma unroll
        for (int o = 16; o; o >>= 1) mx = fmaxf(mx, __shfl_xor_sync(0xffffffffu, mx, o));
        mx *= scale;
        float sum = 0.f;
        for (int j = lane; j < NWIN; j += 32) {
            float e = __expf(ss[r * SSTR + j] * scale - mx);
            ss[r * SSTR + j] = e;
            sum += e;
        }
        #pragma unroll
        for (int o = 16; o; o >>= 1) sum += __shfl_xor_sync(0xffffffffu, sum, o);
        float inv = 1.f / sum;
        for (int j = lane; j < NWIN; j += 32)
            sp[r * SSTR + j] = __float2bfloat16(ss[r * SSTR + j] * inv);
        if (lane < SSTR - NWIN) sp[r * SSTR + NWIN + lane] = __float2bfloat16(0.f);
    }
    __syncthreads();

    float acc[2][4];
    #pragma unroll
    for (int i = 0; i < 2; ++i)
        #pragma unroll
        for (int j = 0; j < 4; ++j) acc[i][j] = 0.f;

    #pragma unroll
    for (int ks = 0; ks < 13; ++ks) {
        uint32_t a0, a1, a2, a3;
        ldm_x4(a0, a1, a2, a3, &sp[(mw * 16 + lr) * SSTR + ks * 16 + lc * 8]);
        uint32_t v0, v1, v2, v3;
        ldm_x4t(v0, v1, v2, v3, &sv[(ks * 16 + lr) * 40 + nh * 16 + lc * 8]);
        mma_bf16(acc[0], a0, a1, a2, a3, v0, v1);
        mma_bf16(acc[1], a0, a1, a2, a3, v2, v3);
    }

    #pragma unroll
    for (int nfl = 0; nfl < 2; ++nfl) {
        int col = nh * 16 + nfl * 8 + 2 * tig;
        float2 gv = *(const float2*)(gamma1 + head * HD + col);
        #pragma unroll
        for (int h = 0; h < 2; ++h) {
            int qi = mw * 16 + gid + h * 8;
            int y = by0 + (qi >> 3), x = bx0 + (qi & 7);
            size_t off = ((size_t)b * PP + (size_t)y * WW + x) * CC + head * HD + col;
            float2 xv = *(const float2*)(xT + off);
            float2 o;
            o.x = xv.x + gv.x * acc[nfl][h * 2 + 0];
            o.y = xv.y + gv.y * acc[nfl][h * 2 + 1];
            *(float2*)(xres + off) = o;
        }
    }
}

// ---------- final: out(NCHW) = xres + gamma2[c]*y ----------
__global__ void k_final(const float* __restrict__ xres, const float* __restrict__ y,
                        const float* __restrict__ gamma2, float* __restrict__ out) {
    __shared__ float t[32][33];
    int b  = blockIdx.z;
    int p0 = blockIdx.x * 32;
    int c0 = blockIdx.y * 32;
    int tx = threadIdx.x, ty = threadIdx.y;
    const float* xb = xres + (size_t)b * PP * CC;
    const float* yb = y    + (size_t)b * PP * CC;
    #pragma unroll
    for (int i = 0; i < 32; i += 8) {
        int p = p0 + ty + i, c = c0 + tx;
        size_t off = (size_t)p * CC + c;
        t[ty + i][tx] = xb[off] + gamma2[c] * yb[off];
    }
    __syncthreads();
    float* ob = out + (size_t)b * CC * PP;
    #pragma unroll
    for (int i = 0; i < 32; i += 8)
        ob[(size_t)(c0 + ty + i) * PP + p0 + tx] = t[tx][ty + i];
}

// ---------------- launcher ----------------
extern "C" void kernel_launch(void* const* d_in, const int* in_sizes, int n_in,
                              void* d_out, int out_size) {
    const float* x      = (const float*)d_in[0];
    const float* g1     = (const float*)d_in[1];
    const float* b1     = (const float*)d_in[2];
    const float* w_q    = (const float*)d_in[3];
    const float* w_kv   = (const float*)d_in[4];
    const float* gamma1 = (const float*)d_in[5];
    const float* g2     = (const float*)d_in[6];
    const float* b2     = (const float*)d_in[7];
    const float* w_fc1  = (const float*)d_in[8];
    const float* b_fc1  = (const float*)d_in[9];
    const float* w_fc2  = (const float*)d_in[10];
    const float* b_fc2  = (const float*)d_in[11];
    const float* gamma2 = (const float*)d_in[12];
    float* out = (float*)d_out;

    float *big, *xres, *yb;
    __nv_bfloat16 *ln16, *w16;
    cudaGetSymbolAddress((void**)&big,  g_big);
    cudaGetSymbolAddress((void**)&ln16, g_ln16);
    cudaGetSymbolAddress((void**)&xres, g_xres);
    cudaGetSymbolAddress((void**)&yb,   g_y);
    cudaGetSymbolAddress((void**)&w16,  g_w16);

    float* xT = big;                                              // fp32 [0, 8M floats)
    __nv_bfloat16* qkv16 = (__nv_bfloat16*)(big + (size_t)ELEM_XC); // bf16 @8M floats (48MB)
    __nv_bfloat16* h1 = (__nv_bfloat16*)big;                      // bf16 overlay [0, 16M floats)

    __nv_bfloat16* wqkv16 = w16;             // [512][1536]
    __nv_bfloat16* wfc116 = w16 + 786432;    // [512][2048]
    __nv_bfloat16* wfc216 = w16 + 1835008;   // [2048][512]

    cudaFuncSetAttribute(k_attn, cudaFuncAttributeMaxDynamicSharedMemorySize, ATT_SMEM_BYTES);
    cudaFuncSetAttribute(k_gemm_bf16, cudaFuncAttributeMaxDynamicSharedMemorySize, GEMM_SMEM);
    cudaFuncSetAttribute(k_tln, cudaFuncAttributeMaxDynamicSharedMemorySize, TLN_SMEM);

    dim3 tb32(32, 8);
    dim3 gT(PP / 32, CC / 32, BATCH);

    // weights -> bf16 (wq,wkv interleave into combined [512][1536])
    k_cvt_str<<<65536 / 256, 256>>>(w_q,   (uint2*)wqkv16, 128, 384, 0);
    k_cvt_str<<<131072 / 256, 256>>>(w_kv, (uint2*)wqkv16, 256, 384, 128);
    k_cvt_str<<<262144 / 256, 256>>>(w_fc1, (uint2*)wfc116, 512, 512, 0);
    k_cvt_str<<<262144 / 256, 256>>>(w_fc2, (uint2*)wfc216, 128, 128, 0);

    // 1) fused NCHW->NHWC transpose + ln1 (writes xT fp32 + ln16 bf16)
    k_tln<<<dim3(PP / 32, BATCH), 256, TLN_SMEM>>>(x, g1, b1, xT, ln16);
    // 2) qkv = ln1 @ [w_q|w_kv]  (bf16 out, N=1536)
    k_gemm_bf16<<<dim3(QKVS / 128, NP / 128), 256, GEMM_SMEM>>>(
        ln16, wqkv16, nullptr, qkv16, NP, QKVS, CC, 0, 1);
    // 3) tensor-core halo attention + fused residual-1
    k_attn<<<dim3(64, NHEAD, BATCH), 256, ATT_SMEM_BYTES>>>(qkv16, xT, gamma1, xres);
    // 4) ln2 -> bf16
    k_ln<<<NP, 128>>>(xres, g2, b2, ln16);
    // 5) fc1 + bias + gelu (bf16 out)
    k_gemm_bf16<<<dim3(MLPH / 128, NP / 128), 256, GEMM_SMEM>>>(
        ln16, wfc116, b_fc1, h1, NP, MLPH, CC, 2, 1);
    // 6) fc2 + bias (fp32 out)
    k_gemm_bf16<<<dim3(CC / 128, NP / 128), 256, GEMM_SMEM>>>(
        h1, wfc216, b_fc2, yb, NP, CC, MLPH, 1, 0);
    // 7) final residual + NHWC -> NCHW
    k_final<<<gT, tb32>>>(xres, yb, gamma2, out);
}

// round 15
// speedup vs baseline: 5.9476x; 1.5561x over previous
#include <cuda_runtime.h>
#include <cuda_bf16.h>
#include <math.h>
#include <stdint.h>

// ---------------- problem constants ----------------
#define BATCH 4
#define CC    512
#define HH    64
#define WW    64
#define PP    (HH*WW)
#define NP    (BATCH*PP)
#define NHEAD 16
#define HD    32
#define BS    8
#define HALO  3
#define WIN   14
#define NWIN  (WIN*WIN)        // 196
#define NKPAD 208
#define MLPH  2048
#define EPSLN 1e-5f
#define QKVS  1536             // combined qkv row stride

// ---------------- scratch ----------------
#define ELEM_XC (NP*CC)
__device__ float          g_big [(size_t)NP*MLPH];   // xT fp32 [0,8M) | qkv16 @8M..20M ; h1 bf16 overlay [0,16M)
__device__ __nv_bfloat16  g_ln16[ELEM_XC];
__device__ float          g_xres[ELEM_XC];
__device__ float          g_y   [ELEM_XC];
// wqkv16 @0 (786432 = 512*1536), wfc1 @786432 (1M), wfc2 @1835008 (1M)
__device__ __nv_bfloat16  g_w16 [2883584];

// ---------------- strided fp32 -> bf16 convert (uint2 = 4 bf16 chunks) ----------------
__global__ void k_cvt_str(const float* __restrict__ in, uint2* __restrict__ out,
                          int cols4, int ostride4, int ooff4) {
    int i = blockIdx.x * blockDim.x + threadIdx.x;
    float4 v = ((const float4*)in)[i];
    __nv_bfloat162 p0 = __floats2bfloat162_rn(v.x, v.y);
    __nv_bfloat162 p1 = __floats2bfloat162_rn(v.z, v.w);
    uint2 o = {*(uint32_t*)&p0, *(uint32_t*)&p1};
    int k = i / cols4, c = i % cols4;
    out[k * ostride4 + ooff4 + c] = o;
}

// ---------------- fused NCHW->NHWC transpose + LayerNorm1 ----------------
#define TLN_SMEM (32*521*4)
__global__ void __launch_bounds__(256)
k_tln(const float* __restrict__ x, const float* __restrict__ g,
      const float* __restrict__ bta, float* __restrict__ xT,
      __nv_bfloat16* __restrict__ ln16) {
    extern __shared__ float s[];   // [32][521]
    int b = blockIdx.y, p0 = blockIdx.x * 32;
    int tid = threadIdx.x;
    const float* xb = x + (size_t)b * CC * PP + p0;
    #pragma unroll
    for (int it = 0; it < 64; ++it) {
        int idx = it * 256 + tid;
        int c = idx >> 5, tp = idx & 31;
        s[tp * 521 + c] = xb[(size_t)c * PP + tp];
    }
    __syncthreads();
    int warp = tid >> 5, lane = tid & 31;
    for (int pi = warp; pi < 32; pi += 8) {
        float sum = 0.f, sq = 0.f;
        #pragma unroll
        for (int j = 0; j < 16; ++j) {
            float v = s[pi * 521 + lane + 32 * j];
            sum += v; sq += v * v;
        }
        #pragma unroll
        for (int o = 16; o; o >>= 1) {
            sum += __shfl_xor_sync(0xffffffffu, sum, o);
            sq  += __shfl_xor_sync(0xffffffffu, sq,  o);
        }
        float mu = sum * (1.0f / CC);
        float rs = rsqrtf(sq * (1.0f / CC) - mu * mu + EPSLN);
        size_t orow = ((size_t)b * PP + p0 + pi) * CC;
        #pragma unroll
        for (int j = 0; j < 4; ++j) {
            int c = lane * 4 + j * 128;
            float4 gv = *(const float4*)(g + c);
            float4 bv = *(const float4*)(bta + c);
            float v0 = s[pi * 521 + c + 0], v1 = s[pi * 521 + c + 1];
            float v2 = s[pi * 521 + c + 2], v3 = s[pi * 521 + c + 3];
            float4 o4 = {v0, v1, v2, v3};
            *(float4*)(xT + orow + c) = o4;
            float l0 = (v0 - mu) * rs * gv.x + bv.x;
            float l1 = (v1 - mu) * rs * gv.y + bv.y;
            float l2 = (v2 - mu) * rs * gv.z + bv.z;
            float l3 = (v3 - mu) * rs * gv.w + bv.w;
            __nv_bfloat162 q0 = __floats2bfloat162_rn(l0, l1);
            __nv_bfloat162 q1 = __floats2bfloat162_rn(l2, l3);
            uint2 pk = {*(uint32_t*)&q0, *(uint32_t*)&q1};
            *(uint2*)(ln16 + orow + c) = pk;
        }
    }
}

// ---------------- LayerNorm (fp32 in, bf16 out) -- ln2 ----------------
__global__ void k_ln(const float* __restrict__ in, const float* __restrict__ g,
                     const float* __restrict__ bta, __nv_bfloat16* __restrict__ out) {
    int pix = blockIdx.x;
    int t   = threadIdx.x;
    const float4* row = (const float4*)(in + (size_t)pix * CC);
    float4 v = row[t];
    float s  = v.x + v.y + v.z + v.w;
    float s2 = v.x*v.x + v.y*v.y + v.z*v.z + v.w*v.w;
    #pragma unroll
    for (int o = 16; o; o >>= 1) {
        s  += __shfl_xor_sync(0xffffffffu, s,  o);
        s2 += __shfl_xor_sync(0xffffffffu, s2, o);
    }
    __shared__ float sh[4][2];
    int warp = t >> 5, lane = t & 31;
    if (lane == 0) { sh[warp][0] = s; sh[warp][1] = s2; }
    __syncthreads();
    s  = sh[0][0] + sh[1][0] + sh[2][0] + sh[3][0];
    s2 = sh[0][1] + sh[1][1] + sh[2][1] + sh[3][1];
    float mu = s * (1.0f / CC);
    float var = s2 * (1.0f / CC) - mu * mu;
    float rs = rsqrtf(var + EPSLN);
    float4 gv = ((const float4*)g)[t];
    float4 bv = ((const float4*)bta)[t];
    float o0 = (v.x - mu) * rs * gv.x + bv.x;
    float o1 = (v.y - mu) * rs * gv.y + bv.y;
    float o2 = (v.z - mu) * rs * gv.z + bv.z;
    float o3 = (v.w - mu) * rs * gv.w + bv.w;
    __nv_bfloat162 p0 = __floats2bfloat162_rn(o0, o1);
    __nv_bfloat162 p1 = __floats2bfloat162_rn(o2, o3);
    uint2 o = {*(uint32_t*)&p0, *(uint32_t*)&p1};
    ((uint2*)(out + (size_t)pix * CC))[t] = o;
}

// ---------------- mma helpers ----------------
__device__ __forceinline__ void mma_bf16(float* c, uint32_t a0, uint32_t a1,
                                         uint32_t a2, uint32_t a3,
                                         uint32_t b0, uint32_t b1) {
    asm volatile(
        "mma.sync.aligned.m16n8k16.row.col.f32.bf16.bf16.f32 "
        "{%0,%1,%2,%3}, {%4,%5,%6,%7}, {%8,%9}, {%0,%1,%2,%3};\n"
        : "+f"(c[0]), "+f"(c[1]), "+f"(c[2]), "+f"(c[3])
        : "r"(a0), "r"(a1), "r"(a2), "r"(a3), "r"(b0), "r"(b1));
}
__device__ __forceinline__ void cp_async16(uint32_t dst, const void* src) {
    asm volatile("cp.async.cg.shared.global [%0], [%1], 16;\n" :: "r"(dst), "l"(src));
}
__device__ __forceinline__ void ldm_x4(uint32_t& a0, uint32_t& a1, uint32_t& a2,
                                       uint32_t& a3, const void* p) {
    uint32_t addr = (uint32_t)__cvta_generic_to_shared(p);
    asm volatile("ldmatrix.sync.aligned.m8n8.x4.shared.b16 {%0,%1,%2,%3}, [%4];\n"
                 : "=r"(a0), "=r"(a1), "=r"(a2), "=r"(a3) : "r"(addr));
}
__device__ __forceinline__ void ldm_x4t(uint32_t& a0, uint32_t& a1, uint32_t& a2,
                                        uint32_t& a3, const void* p) {
    uint32_t addr = (uint32_t)__cvta_generic_to_shared(p);
    asm volatile("ldmatrix.sync.aligned.m8n8.x4.trans.shared.b16 {%0,%1,%2,%3}, [%4];\n"
                 : "=r"(a0), "=r"(a1), "=r"(a2), "=r"(a3) : "r"(addr));
}
__device__ __forceinline__ void ldm_x2(uint32_t& b0, uint32_t& b1, const void* p) {
    uint32_t addr = (uint32_t)__cvta_generic_to_shared(p);
    asm volatile("ldmatrix.sync.aligned.m8n8.x2.shared.b16 {%0,%1}, [%2];\n"
                 : "=r"(b0), "=r"(b1) : "r"(addr));
}

// ---------------- bf16 TC GEMM: 3-stage cp.async + ldmatrix (R10, proven) ----------------
#define ASTRIDE 40
#define BSTRIDE 136
#define GEMM_SMEM ((3*128*ASTRIDE + 3*32*BSTRIDE) * 2)   // 56832 bytes

__global__ void __launch_bounds__(256, 2)
k_gemm_bf16(const __nv_bfloat16* __restrict__ A, const __nv_bfloat16* __restrict__ B,
            const float* __restrict__ bias, void* __restrict__ Cout,
            int M, int N, int K, int epi, int out_bf16) {
    extern __shared__ __align__(16) __nv_bfloat16 dsm[];
    __nv_bfloat16* Asm = dsm;
    __nv_bfloat16* Bsm = dsm + 3 * 128 * ASTRIDE;

    int tid = threadIdx.x;
    int bm = blockIdx.y << 7, bn = blockIdx.x << 7;

    auto copy_tile = [&](int buf, int k0) {
        __nv_bfloat16* Ab = Asm + buf * 128 * ASTRIDE;
        __nv_bfloat16* Bb = Bsm + buf * 32 * BSTRIDE;
        #pragma unroll
        for (int i = 0; i < 2; ++i) {
            int c = tid + i * 256;
            int ar = c >> 2, a8 = (c & 3) * 8;
            cp_async16((uint32_t)__cvta_generic_to_shared(&Ab[ar * ASTRIDE + a8]),
                       A + (size_t)(bm + ar) * K + k0 + a8);
            int br = c >> 4, b8 = (c & 15) * 8;
            cp_async16((uint32_t)__cvta_generic_to_shared(&Bb[br * BSTRIDE + b8]),
                       B + (size_t)(k0 + br) * N + bn + b8);
        }
        asm volatile("cp.async.commit_group;\n");
    };

    int nT = K >> 5;
    copy_tile(0, 0);
    copy_tile(1, 32);

    float acc[4][4][4];
    #pragma unroll
    for (int a = 0; a < 4; ++a)
        #pragma unroll
        for (int b = 0; b < 4; ++b)
            #pragma unroll
            for (int cI = 0; cI < 4; ++cI) acc[a][b][cI] = 0.f;

    int lane = tid & 31, warp = tid >> 5;
    int wm = (warp & 1) * 64;
    int wn = (warp >> 1) * 32;
    int gid = lane >> 2, tig = lane & 3;
    int lr = lane & 15, lc = lane >> 4;

    int cur = 0;
    for (int t = 0; t < nT; ++t) {
        if (t + 1 < nT) { asm volatile("cp.async.wait_group 1;\n"); }
        else            { asm volatile("cp.async.wait_group 0;\n"); }
        __syncthreads();
        if (t + 2 < nT) {
            int nb = cur + 2; if (nb >= 3) nb -= 3;
            copy_tile(nb, (t + 2) * 32);
        }
        __nv_bfloat16* Ab = Asm + cur * 128 * ASTRIDE;
        __nv_bfloat16* Bb = Bsm + cur * 32 * BSTRIDE;

        #pragma unroll
        for (int ks = 0; ks < 2; ++ks) {
            int kb = ks * 16;
            uint32_t bfr[4][2];
            #pragma unroll
            for (int h = 0; h < 2; ++h) {
                uint32_t r0, r1, r2, r3;
                ldm_x4t(r0, r1, r2, r3, &Bb[(kb + lr) * BSTRIDE + wn + h * 16 + lc * 8]);
                bfr[h * 2 + 0][0] = r0; bfr[h * 2 + 0][1] = r1;
                bfr[h * 2 + 1][0] = r2; bfr[h * 2 + 1][1] = r3;
            }
            #pragma unroll
            for (int mf = 0; mf < 4; ++mf) {
                uint32_t a0, a1, a2, a3;
                ldm_x4(a0, a1, a2, a3, &Ab[(wm + mf * 16 + lr) * ASTRIDE + kb + lc * 8]);
                #pragma unroll
                for (int nf = 0; nf < 4; ++nf)
                    mma_bf16(acc[mf][nf], a0, a1, a2, a3, bfr[nf][0], bfr[nf][1]);
            }
        }
        if (++cur == 3) cur = 0;
    }

    #pragma unroll
    for (int mf = 0; mf < 4; ++mf) {
        #pragma unroll
        for (int nf = 0; nf < 4; ++nf) {
            int row0 = bm + wm + mf * 16 + gid;
            int col  = bn + wn + nf * 8 + 2 * tig;
            float v[4] = {acc[mf][nf][0], acc[mf][nf][1],
                          acc[mf][nf][2], acc[mf][nf][3]};
            if (epi >= 1) {
                float bb0 = bias[col], bb1 = bias[col + 1];
                v[0] += bb0; v[1] += bb1; v[2] += bb0; v[3] += bb1;
            }
            if (epi == 2) {
                #pragma unroll
                for (int i = 0; i < 4; ++i)
                    v[i] = 0.5f * v[i] * (1.f + erff(v[i] * 0.70710678118654752f));
            }
            if (out_bf16) {
                __nv_bfloat16* C16 = (__nv_bfloat16*)Cout;
                __nv_bfloat162 lo = __floats2bfloat162_rn(v[0], v[1]);
                __nv_bfloat162 hi = __floats2bfloat162_rn(v[2], v[3]);
                *(uint32_t*)(C16 + (size_t)row0 * N + col)       = *(uint32_t*)&lo;
                *(uint32_t*)(C16 + (size_t)(row0 + 8) * N + col) = *(uint32_t*)&hi;
            } else {
                float* C = (float*)Cout;
                float2 lo = {v[0], v[1]}, hi = {v[2], v[3]};
                *(float2*)(C + (size_t)row0 * N + col)       = lo;
                *(float2*)(C + (size_t)(row0 + 8) * N + col) = hi;
            }
        }
    }
}

// ---------------- tensor-core halo attention, register softmax ----------------
// smem: sq 0..5120 | sk 5120..21760 | sv 21760..38400 | P(bf16) 38400..66048 | red 66048..67072
#define ATT_SMEM_BYTES 67072
#define SSTR 216

__global__ void __launch_bounds__(256)
k_attn(const __nv_bfloat16* __restrict__ qkv, const float* __restrict__ xT,
       const float* __restrict__ gamma1, float* __restrict__ xres) {
    extern __shared__ char smem[];
    __nv_bfloat16* sq = (__nv_bfloat16*)smem;
    __nv_bfloat16* sk = (__nv_bfloat16*)(smem + 5120);
    __nv_bfloat16* sv = (__nv_bfloat16*)(smem + 21760);
    __nv_bfloat16* sp = (__nv_bfloat16*)(smem + 38400);
    float*        red = (float*)        (smem + 66048);   // [64][2 halves][2: max,sum]

    int blk = blockIdx.x, head = blockIdx.y, b = blockIdx.z;
    int by0 = (blk >> 3) * BS, bx0 = (blk & 7) * BS;
    int tid = threadIdx.x;
    int lane = tid & 31, warp = tid >> 5;

    {
        int r = tid >> 2, d8 = (tid & 3) * 8;
        int y = by0 + (r >> 3), x = bx0 + (r & 7);
        *(uint4*)&sq[r * 40 + d8] =
            *(const uint4*)(qkv + ((size_t)b * PP + (size_t)y * WW + x) * QKVS + head * HD + d8);
    }
    for (int c = tid; c < NKPAD * 4; c += 256) {
        int r = c >> 2, d8 = (c & 3) * 8;
        int y = by0 - HALO + r / WIN;
        int x = bx0 - HALO + r % WIN;
        uint4 kk = {0,0,0,0}, vv = {0,0,0,0};
        if (r < NWIN && y >= 0 && y < HH && x >= 0 && x < WW) {
            const __nv_bfloat16* base =
                qkv + ((size_t)b * PP + (size_t)y * WW + x) * QKVS + CC + head * HD + d8;
            kk = *(const uint4*)base;
            vv = *(const uint4*)(base + CC);
        }
        *(uint4*)&sk[r * 40 + d8] = kk;
        *(uint4*)&sv[r * 40 + d8] = vv;
    }
    __syncthreads();

    int mw = warp & 3, nh = warp >> 2;
    int lr = lane & 15, lc = lane >> 4;
    int gid = lane >> 2, tig = lane & 3;
    int r2 = lane & 7, sel = (lane >> 3) & 1;
    int row1 = mw * 16 + gid, row2 = row1 + 8;

    // ---- S = Q K^T, accumulators stay in registers ----
    float accS[13][4];
    #pragma unroll
    for (int nf = 0; nf < 13; ++nf)
        #pragma unroll
        for (int i = 0; i < 4; ++i) accS[nf][i] = 0.f;
    #pragma unroll
    for (int ks = 0; ks < 2; ++ks) {
        uint32_t a0, a1, a2, a3;
        ldm_x4(a0, a1, a2, a3, &sq[(mw * 16 + lr) * 40 + ks * 16 + lc * 8]);
        #pragma unroll
        for (int nf = 0; nf < 13; ++nf) {
            int n0 = (nh * 13 + nf) * 8;
            uint32_t b0, b1;
            ldm_x2(b0, b1, &sk[(n0 + r2) * 40 + ks * 16 + sel * 8]);
            mma_bf16(accS[nf], a0, a1, a2, a3, b0, b1);
        }
    }

    // ---- register softmax ----
    const float scale = 0.1767766952966369f;  // 1/sqrt(32)
    // phase A: per-thread masked max, quad-reduce, write red max slots
    float m1 = -1e30f, m2 = -1e30f;
    #pragma unroll
    for (int nf = 0; nf < 13; ++nf) {
        int c0 = (nh * 13 + nf) * 8 + 2 * tig;
        if (c0 < NWIN)     { m1 = fmaxf(m1, accS[nf][0]); m2 = fmaxf(m2, accS[nf][2]); }
        if (c0 + 1 < NWIN) { m1 = fmaxf(m1, accS[nf][1]); m2 = fmaxf(m2, accS[nf][3]); }
    }
    m1 = fmaxf(m1, __shfl_xor_sync(0xffffffffu, m1, 1));
    m1 = fmaxf(m1, __shfl_xor_sync(0xffffffffu, m1, 2));
    m2 = fmaxf(m2, __shfl_xor_sync(0xffffffffu, m2, 1));
    m2 = fmaxf(m2, __shfl_xor_sync(0xffffffffu, m2, 2));
    if (tig == 0) {
        red[(row1 * 2 + nh) * 2 + 0] = m1;
        red[(row2 * 2 + nh) * 2 + 0] = m2;
    }
    __syncthreads();
    // phase B: global max, exp, partial sums, write red sum slots
    float g1 = fmaxf(red[(row1 * 2 + 0) * 2], red[(row1 * 2 + 1) * 2]);
    float g2 = fmaxf(red[(row2 * 2 + 0) * 2], red[(row2 * 2 + 1) * 2]);
    float s1 = 0.f, s2 = 0.f;
    #pragma unroll
    for (int nf = 0; nf < 13; ++nf) {
        int c0 = (nh * 13 + nf) * 8 + 2 * tig;
        float e;
        e = (c0 < NWIN)     ? __expf((accS[nf][0] - g1) * scale) : 0.f; accS[nf][0] = e; s1 += e;
        e = (c0 + 1 < NWIN) ? __expf((accS[nf][1] - g1) * scale) : 0.f; accS[nf][1] = e; s1 += e;
        e = (c0 < NWIN)     ? __expf((accS[nf][2] - g2) * scale) : 0.f; accS[nf][2] = e; s2 += e;
        e = (c0 + 1 < NWIN) ? __expf((accS[nf][3] - g2) * scale) : 0.f; accS[nf][3] = e; s2 += e;
    }
    s1 += __shfl_xor_sync(0xffffffffu, s1, 1);
    s1 += __shfl_xor_sync(0xffffffffu, s1, 2);
    s2 += __shfl_xor_sync(0xffffffffu, s2, 1);
    s2 += __shfl_xor_sync(0xffffffffu, s2, 2);
    if (tig == 0) {
        red[(row1 * 2 + nh) * 2 + 1] = s1;
        red[(row2 * 2 + nh) * 2 + 1] = s2;
    }
    __syncthreads();
    // phase C: normalize, write P bf16
    float inv1 = 1.f / (red[(row1 * 2 + 0) * 2 + 1] + red[(row1 * 2 + 1) * 2 + 1]);
    float inv2 = 1.f / (red[(row2 * 2 + 0) * 2 + 1] + red[(row2 * 2 + 1) * 2 + 1]);
    #pragma unroll
    for (int nf = 0; nf < 13; ++nf) {
        int c0 = (nh * 13 + nf) * 8 + 2 * tig;
        __nv_bfloat162 p1 = __floats2bfloat162_rn(accS[nf][0] * inv1, accS[nf][1] * inv1);
        __nv_bfloat162 p2 = __floats2bfloat162_rn(accS[nf][2] * inv2, accS[nf][3] * inv2);
        *(uint32_t*)&sp[row1 * SSTR + c0] = *(uint32_t*)&p1;
        *(uint32_t*)&sp[row2 * SSTR + c0] = *(uint32_t*)&p2;
    }
    __syncthreads();

    // ---- O = P V (64 x 32), fused gamma1-residual ----
    float acc[2][4];
    #pragma unroll
    for (int i = 0; i < 2; ++i)
        #pragma unroll
        for (int j = 0; j < 4; ++j) acc[i][j] = 0.f;

    #pragma unroll
    for (int ks = 0; ks < 13; ++ks) {
        uint32_t a0, a1, a2, a3;
        ldm_x4(a0, a1, a2, a3, &sp[(mw * 16 + lr) * SSTR + ks * 16 + lc * 8]);
        uint32_t v0, v1, v2, v3;
        ldm_x4t(v0, v1, v2, v3, &sv[(ks * 16 + lr) * 40 + nh * 16 + lc * 8]);
        mma_bf16(acc[0], a0, a1, a2, a3, v0, v1);
        mma_bf16(acc[1], a0, a1, a2, a3, v2, v3);
    }

    #pragma unroll
    for (int nfl = 0; nfl < 2; ++nfl) {
        int col = nh * 16 + nfl * 8 + 2 * tig;
        float2 gv = *(const float2*)(gamma1 + head * HD + col);
        #pragma unroll
        for (int h = 0; h < 2; ++h) {
            int qi = mw * 16 + gid + h * 8;
            int y = by0 + (qi >> 3), x = bx0 + (qi & 7);
            size_t off = ((size_t)b * PP + (size_t)y * WW + x) * CC + head * HD + col;
            float2 xv = *(const float2*)(xT + off);
            float2 o;
            o.x = xv.x + gv.x * acc[nfl][h * 2 + 0];
            o.y = xv.y + gv.y * acc[nfl][h * 2 + 1];
            *(float2*)(xres + off) = o;
        }
    }
}

// ---------- final: out(NCHW) = xres + gamma2[c]*y ----------
__global__ void k_final(const float* __restrict__ xres, const float* __restrict__ y,
                        const float* __restrict__ gamma2, float* __restrict__ out) {
    __shared__ float t[32][33];
    int b  = blockIdx.z;
    int p0 = blockIdx.x * 32;
    int c0 = blockIdx.y * 32;
    int tx = threadIdx.x, ty = threadIdx.y;
    const float* xb = xres + (size_t)b * PP * CC;
    const float* yb = y    + (size_t)b * PP * CC;
    #pragma unroll
    for (int i = 0; i < 32; i += 8) {
        int p = p0 + ty + i, c = c0 + tx;
        size_t off = (size_t)p * CC + c;
        t[ty + i][tx] = xb[off] + gamma2[c] * yb[off];
    }
    __syncthreads();
    float* ob = out + (size_t)b * CC * PP;
    #pragma unroll
    for (int i = 0; i < 32; i += 8)
        ob[(size_t)(c0 + ty + i) * PP + p0 + tx] = t[tx][ty + i];
}

// ---------------- launcher ----------------
extern "C" void kernel_launch(void* const* d_in, const int* in_sizes, int n_in,
                              void* d_out, int out_size) {
    const float* x      = (const float*)d_in[0];
    const float* g1     = (const float*)d_in[1];
    const float* b1     = (const float*)d_in[2];
    const float* w_q    = (const float*)d_in[3];
    const float* w_kv   = (const float*)d_in[4];
    const float* gamma1 = (const float*)d_in[5];
    const float* g2     = (const float*)d_in[6];
    const float* b2     = (const float*)d_in[7];
    const float* w_fc1  = (const float*)d_in[8];
    const float* b_fc1  = (const float*)d_in[9];
    const float* w_fc2  = (const float*)d_in[10];
    const float* b_fc2  = (const float*)d_in[11];
    const float* gamma2 = (const float*)d_in[12];
    float* out = (float*)d_out;

    float *big, *xres, *yb;
    __nv_bfloat16 *ln16, *w16;
    cudaGetSymbolAddress((void**)&big,  g_big);
    cudaGetSymbolAddress((void**)&ln16, g_ln16);
    cudaGetSymbolAddress((void**)&xres, g_xres);
    cudaGetSymbolAddress((void**)&yb,   g_y);
    cudaGetSymbolAddress((void**)&w16,  g_w16);

    float* xT = big;
    __nv_bfloat16* qkv16 = (__nv_bfloat16*)(big + (size_t)ELEM_XC);
    __nv_bfloat16* h1 = (__nv_bfloat16*)big;

    __nv_bfloat16* wqkv16 = w16;             // [512][1536]
    __nv_bfloat16* wfc116 = w16 + 786432;    // [512][2048]
    __nv_bfloat16* wfc216 = w16 + 1835008;   // [2048][512]

    cudaFuncSetAttribute(k_attn, cudaFuncAttributeMaxDynamicSharedMemorySize, ATT_SMEM_BYTES);
    cudaFuncSetAttribute(k_gemm_bf16, cudaFuncAttributeMaxDynamicSharedMemorySize, GEMM_SMEM);
    cudaFuncSetAttribute(k_tln, cudaFuncAttributeMaxDynamicSharedMemorySize, TLN_SMEM);

    dim3 tb32(32, 8);
    dim3 gT(PP / 32, CC / 32, BATCH);

    // weights -> bf16 (wq,wkv interleave into combined [512][1536])
    k_cvt_str<<<65536 / 256, 256>>>(w_q,   (uint2*)wqkv16, 128, 384, 0);
    k_cvt_str<<<131072 / 256, 256>>>(w_kv, (uint2*)wqkv16, 256, 384, 128);
    k_cvt_str<<<262144 / 256, 256>>>(w_fc1, (uint2*)wfc116, 512, 512, 0);
    k_cvt_str<<<262144 / 256, 256>>>(w_fc2, (uint2*)wfc216, 128, 128, 0);

    // 1) fused NCHW->NHWC transpose + ln1
    k_tln<<<dim3(PP / 32, BATCH), 256, TLN_SMEM>>>(x, g1, b1, xT, ln16);
    // 2) qkv = ln1 @ [w_q|w_kv]  (bf16 out, N=1536)
    k_gemm_bf16<<<dim3(QKVS / 128, NP / 128), 256, GEMM_SMEM>>>(
        ln16, wqkv16, nullptr, qkv16, NP, QKVS, CC, 0, 1);
    // 3) tensor-core halo attention + fused residual-1 (register softmax)
    k_attn<<<dim3(64, NHEAD, BATCH), 256, ATT_SMEM_BYTES>>>(qkv16, xT, gamma1, xres);
    // 4) ln2 -> bf16
    k_ln<<<NP, 128>>>(xres, g2, b2, ln16);
    // 5) fc1 + bias + gelu (bf16 out)
    k_gemm_bf16<<<dim3(MLPH / 128, NP / 128), 256, GEMM_SMEM>>>(
        ln16, wfc116, b_fc1, h1, NP, MLPH, CC, 2, 1);
    // 6) fc2 + bias (fp32 out)
    k_gemm_bf16<<<dim3(CC / 128, NP / 128), 256, GEMM_SMEM>>>(
        h1, wfc216, b_fc2, yb, NP, CC, MLPH, 1, 0);
    // 7) final residual + NHWC -> NCHW
    k_final<<<gT, tb32>>>(xres, yb, gamma2, out);
}